// round 7
// baseline (speedup 1.0000x reference)
#include <cuda_runtime.h>
#include <math.h>

#define R_REG 2000
#define NHEAD 4
#define DIM   128
#define DH    32
#define NMAX  500000
#define WPITCH 132   // smem pitch (floats) for conflict-free float4 matvec reads
#define HIST_CHUNK 8192

// ---------------- scratch (device globals; no allocation allowed) ----------------
__device__ float d_q[DIM];                      // PMA seed query (flattened)
__device__ float d_A[NHEAD * DIM];              // folded score matrix (incl 1/sqrt(D))
__device__ float d_c[NHEAD];                    // folded score bias
__device__ int   d_hist[R_REG];                 // zeroed by k_scan after reading (replay-safe)
__device__ int   d_starts[R_REG + 1];
__device__ int   d_cursor[R_REG];
__device__ int   d_order[NMAX];                 // point index, sorted by zone
__device__ __align__(16) float4 d_esort[NMAX];  // exp-weights, sorted by zone (same positions)
__device__ __align__(16) float d_u[R_REG * NHEAD * DIM];  // normalized weighted sums of x
__device__ float d_flag[R_REG];                 // 1 if region nonempty
__device__ float d_hbuf[R_REG * DIM];           // GCN h = O @ Wg^T
__device__ float d_deg[R_REG];

// ---------------- K0: init + smem-privatized zone histogram + seed-query setup ----------------
__global__ void k_init_setup(const float* __restrict__ bg, float* __restrict__ out,
                             const float* __restrict__ S, const float* __restrict__ Wq,
                             const float* __restrict__ bq, const float* __restrict__ Wk,
                             const float* __restrict__ bk, const int* __restrict__ zone,
                             int N, int nbI, int nbH) {
    int t = threadIdx.x;
    int b = blockIdx.x;
    if (b < nbI) {
        int i = b * blockDim.x + t;
        if (i < R_REG * DIM) out[i] = bg[i & (DIM - 1)];
        if (i < R_REG) d_deg[i] = 1.0f;   // deg starts at 1 (self loop)
    } else if (b < nbI + nbH) {
        // privatized histogram: one smem pass per 8192 points, then sparse global flush
        __shared__ int hs[R_REG];
        for (int i = t; i < R_REG; i += 256) hs[i] = 0;
        __syncthreads();
        int base = (b - nbI) * HIST_CHUNK;
        int lim = min(HIST_CHUNK, N - base);
        for (int i = t; i < lim; i += 256) atomicAdd(&hs[zone[base + i]], 1);
        __syncthreads();
        for (int i = t; i < R_REG; i += 256) {
            int v = hs[i];
            if (v) atomicAdd(&d_hist[i], v);
        }
    } else {
        // ---- setup: q = Wq S + bq ; A = (q^T Wk)/sqrt(D) ----
        __shared__ float S_s[DIM];
        __shared__ float q_s[DIM];
        if (t < DIM) S_s[t] = S[t];
        __syncthreads();
        if (t < DIM) {
            float acc = bq[t];
            const float4* wrow = (const float4*)(Wq + t * DIM);
            const float4* s4 = (const float4*)S_s;
            #pragma unroll
            for (int i = 0; i < DIM / 4; i++) {
                float4 w = wrow[i]; float4 s = s4[i];
                acc = fmaf(w.x, s.x, acc); acc = fmaf(w.y, s.y, acc);
                acc = fmaf(w.z, s.z, acc); acc = fmaf(w.w, s.w, acc);
            }
            q_s[t] = acc;
            d_q[t] = acc;
        }
        __syncthreads();
        if (t < DIM) {
            const float invsq = 0.08838834764831845f;  // 1/sqrt(128)
            for (int h = 0; h < NHEAD; h++) {
                float a = 0.f;
                #pragma unroll 8
                for (int dh = 0; dh < DH; dh++)
                    a = fmaf(q_s[h * DH + dh], Wk[(h * DH + dh) * DIM + t], a);
                d_A[h * DIM + t] = a * invsq;
            }
            if (t < NHEAD) {
                float cc = 0.f;
                for (int dh = 0; dh < DH; dh++) cc = fmaf(q_s[t * DH + dh], bk[t * DH + dh], cc);
                d_c[t] = cc * invsq;
            }
        }
    }
}

// ---------------- K1: exclusive scan of histogram (single block); resets hist for next replay ----------------
__global__ void k_scan() {
    __shared__ int wsum[8];
    int t = threadIdx.x;                 // 256 threads, 8 elems each
    int base = t * 8;
    int vals[8]; int s = 0;
    #pragma unroll
    for (int i = 0; i < 8; i++) {
        int idx = base + i;
        int v = 0;
        if (idx < R_REG) { v = d_hist[idx]; d_hist[idx] = 0; }  // read + reset (replay-safe)
        vals[i] = s; s += v;
    }
    int lane = t & 31, w = t >> 5;
    int inc = s;
    #pragma unroll
    for (int off = 1; off < 32; off <<= 1) {
        int o = __shfl_up_sync(0xffffffffu, inc, off);
        if (lane >= off) inc += o;
    }
    if (lane == 31) wsum[w] = inc;
    __syncthreads();
    if (t == 0) {
        int acc = 0;
        for (int i = 0; i < 8; i++) { int v = wsum[i]; wsum[i] = acc; acc += v; }
        d_starts[R_REG] = acc;
    }
    __syncthreads();
    int texcl = inc - s + wsum[w];
    #pragma unroll
    for (int i = 0; i < 8; i++) {
        int idx = base + i;
        if (idx < R_REG) {
            int st = texcl + vals[i];
            d_starts[idx] = st;
            d_cursor[idx] = st;
        }
    }
}

// 4-head warp reduction in 9 shfls; lanes 0,8,16,24 return full sums for heads 0..3
__device__ __forceinline__ float headred(float s0, float s1, float s2, float s3, int lane) {
    float o0 = __shfl_xor_sync(0xffffffffu, s0, 16);
    float o1 = __shfl_xor_sync(0xffffffffu, s1, 16);
    float o2 = __shfl_xor_sync(0xffffffffu, s2, 16);
    float o3 = __shfl_xor_sync(0xffffffffu, s3, 16);
    float t0, t1;
    if (lane < 16) { t0 = s0 + o0; t1 = s1 + o1; } else { t0 = s2 + o2; t1 = s3 + o3; }
    float p0 = __shfl_xor_sync(0xffffffffu, t0, 8);
    float p1 = __shfl_xor_sync(0xffffffffu, t1, 8);
    float v = ((lane & 8) == 0) ? (t0 + p0) : (t1 + p1);
    v += __shfl_xor_sync(0xffffffffu, v, 4);
    v += __shfl_xor_sync(0xffffffffu, v, 2);
    v += __shfl_xor_sync(0xffffffffu, v, 1);
    return v;
}

// per-point tail of k_scores: gather 4 head-sums to lane 0, exp, scatter-write
__device__ __forceinline__ void score_emit(float v, int n, const int* __restrict__ zone,
                                           float c0, float c1, float c2, float c3, int lane) {
    // v holds head h's full sum on lanes 0,8,16,24
    float ex = __shfl_sync(0xffffffffu, v, 0);
    float ey = __shfl_sync(0xffffffffu, v, 8);
    float ez = __shfl_sync(0xffffffffu, v, 16);
    float ew = __shfl_sync(0xffffffffu, v, 24);
    if (lane == 0) {
        // scores have tiny variance: unshifted exp is safe; softmax is shift-invariant
        float4 e = make_float4(expf(ex + c0), expf(ey + c1), expf(ez + c2), expf(ew + c3));
        int z = zone[n];
        int pos = atomicAdd(&d_cursor[z], 1);
        d_order[pos] = n;
        d_esort[pos] = e;
    }
}

// ---------------- K2: streaming scores + fused counting-sort scatter (4 pts/warp) + fused deg ----------------
__global__ void __launch_bounds__(256) k_scores(const float* __restrict__ x,
                                                const int* __restrict__ zone,
                                                const int* __restrict__ adj,
                                                int N, int E, int nbS) {
    if ((int)blockIdx.x >= nbS) {
        // fused GCN degree count (independent work, saves a launch)
        int e = (blockIdx.x - nbS) * blockDim.x + threadIdx.x;
        if (e < E) atomicAdd(&d_deg[adj[E + e]], 1.0f);
        return;
    }
    int warp_id = (blockIdx.x * blockDim.x + threadIdx.x) >> 5;
    int lane = threadIdx.x & 31;
    int n0 = warp_id * 4;
    if (n0 >= N) return;                 // warp-uniform
    // 4 independent 512B row loads up-front (2KB in flight per warp)
    const float4* x4 = (const float4*)x;
    float4 z4 = make_float4(0.f, 0.f, 0.f, 0.f);
    float4 xv0 = x4[(size_t)n0 * 32 + lane];
    float4 xv1 = (n0 + 1 < N) ? x4[(size_t)(n0 + 1) * 32 + lane] : z4;
    float4 xv2 = (n0 + 2 < N) ? x4[(size_t)(n0 + 2) * 32 + lane] : z4;
    float4 xv3 = (n0 + 3 < N) ? x4[(size_t)(n0 + 3) * 32 + lane] : z4;
    const float4* A4 = (const float4*)d_A;
    float4 a0 = A4[0 * 32 + lane], a1 = A4[1 * 32 + lane];
    float4 a2 = A4[2 * 32 + lane], a3 = A4[3 * 32 + lane];
    float c0 = d_c[0], c1 = d_c[1], c2 = d_c[2], c3 = d_c[3];

    #define DOT4(a, v) ((a).x*(v).x + (a).y*(v).y + (a).z*(v).z + (a).w*(v).w)
    float v0 = headred(DOT4(a0,xv0), DOT4(a1,xv0), DOT4(a2,xv0), DOT4(a3,xv0), lane);
    float v1 = headred(DOT4(a0,xv1), DOT4(a1,xv1), DOT4(a2,xv1), DOT4(a3,xv1), lane);
    float v2 = headred(DOT4(a0,xv2), DOT4(a1,xv2), DOT4(a2,xv2), DOT4(a3,xv2), lane);
    float v3 = headred(DOT4(a0,xv3), DOT4(a1,xv3), DOT4(a2,xv3), DOT4(a3,xv3), lane);
    #undef DOT4

    score_emit(v0, n0, zone, c0, c1, c2, c3, lane);
    if (n0 + 1 < N) score_emit(v1, n0 + 1, zone, c0, c1, c2, c3, lane);
    if (n0 + 2 < N) score_emit(v2, n0 + 2, zone, c0, c1, c2, c3, lane);
    if (n0 + 3 < N) score_emit(v3, n0 + 3, zone, c0, c1, c2, c3, lane);
}

// ---------------- K3: per-region weighted accumulation of x (2 pts/warp/iter, float4 lanes) ----------------
__global__ void __launch_bounds__(128) k_accum(const float* __restrict__ x) {
    int r = blockIdx.x;
    int t = threadIdx.x;
    int w = t >> 5, lane = t & 31;
    int start = d_starts[r], end = d_starts[r + 1];
    const float4* x4 = (const float4*)x;
    float4 a0 = make_float4(0.f,0.f,0.f,0.f), a1 = a0, a2 = a0, a3 = a0;
    float dn0 = 0.f, dn1 = 0.f, dn2 = 0.f, dn3 = 0.f;
    // warp w handles points {start+2w, start+2w+1}, stride 8 -> 2 indep gathers/iter
    #pragma unroll 2
    for (int p = start + 2 * w; p < end; p += 8) {
        bool h1 = (p + 1 < end);
        int n0 = __ldg(&d_order[p]);
        int n1 = h1 ? __ldg(&d_order[p + 1]) : n0;     // dup load if tail; e1=0 cancels it
        float4 e0 = d_esort[p];                        // dense, no n-dependency
        float4 e1 = h1 ? d_esort[p + 1] : make_float4(0.f,0.f,0.f,0.f);
        float4 xv0 = __ldg(&x4[(size_t)n0 * 32 + lane]);
        float4 xv1 = __ldg(&x4[(size_t)n1 * 32 + lane]);
        a0.x = fmaf(e0.x, xv0.x, a0.x); a0.y = fmaf(e0.x, xv0.y, a0.y);
        a0.z = fmaf(e0.x, xv0.z, a0.z); a0.w = fmaf(e0.x, xv0.w, a0.w);
        a1.x = fmaf(e0.y, xv0.x, a1.x); a1.y = fmaf(e0.y, xv0.y, a1.y);
        a1.z = fmaf(e0.y, xv0.z, a1.z); a1.w = fmaf(e0.y, xv0.w, a1.w);
        a2.x = fmaf(e0.z, xv0.x, a2.x); a2.y = fmaf(e0.z, xv0.y, a2.y);
        a2.z = fmaf(e0.z, xv0.z, a2.z); a2.w = fmaf(e0.z, xv0.w, a2.w);
        a3.x = fmaf(e0.w, xv0.x, a3.x); a3.y = fmaf(e0.w, xv0.y, a3.y);
        a3.z = fmaf(e0.w, xv0.z, a3.z); a3.w = fmaf(e0.w, xv0.w, a3.w);
        dn0 += e0.x; dn1 += e0.y; dn2 += e0.z; dn3 += e0.w;
        a0.x = fmaf(e1.x, xv1.x, a0.x); a0.y = fmaf(e1.x, xv1.y, a0.y);
        a0.z = fmaf(e1.x, xv1.z, a0.z); a0.w = fmaf(e1.x, xv1.w, a0.w);
        a1.x = fmaf(e1.y, xv1.x, a1.x); a1.y = fmaf(e1.y, xv1.y, a1.y);
        a1.z = fmaf(e1.y, xv1.z, a1.z); a1.w = fmaf(e1.y, xv1.w, a1.w);
        a2.x = fmaf(e1.z, xv1.x, a2.x); a2.y = fmaf(e1.z, xv1.y, a2.y);
        a2.z = fmaf(e1.z, xv1.z, a2.z); a2.w = fmaf(e1.z, xv1.w, a2.w);
        a3.x = fmaf(e1.w, xv1.x, a3.x); a3.y = fmaf(e1.w, xv1.y, a3.y);
        a3.z = fmaf(e1.w, xv1.z, a3.z); a3.w = fmaf(e1.w, xv1.w, a3.w);
        dn0 += e1.x; dn1 += e1.y; dn2 += e1.z; dn3 += e1.w;
    }
    // cross-warp combine in smem: part[warp][head][lane] (float4 = dims 4*lane..4*lane+3)
    __shared__ float4 part[4][4][32];
    __shared__ float pdn[4][4];
    part[w][0][lane] = a0; part[w][1][lane] = a1;
    part[w][2][lane] = a2; part[w][3][lane] = a3;
    if (lane == 0) { pdn[w][0] = dn0; pdn[w][1] = dn1; pdn[w][2] = dn2; pdn[w][3] = dn3; }
    __syncthreads();
    // thread t = (h=w, lane) finalizes head w
    int h = w;
    float4 s0 = part[0][h][lane], s1 = part[1][h][lane];
    float4 s2 = part[2][h][lane], s3 = part[3][h][lane];
    float4 u;
    u.x = s0.x + s1.x + s2.x + s3.x;
    u.y = s0.y + s1.y + s2.y + s3.y;
    u.z = s0.z + s1.z + s2.z + s3.z;
    u.w = s0.w + s1.w + s2.w + s3.w;
    float dn = pdn[0][h] + pdn[1][h] + pdn[2][h] + pdn[3][h];
    float inv = dn > 0.f ? 1.0f / dn : 0.f;
    u.x *= inv; u.y *= inv; u.z *= inv; u.w *= inv;
    ((float4*)d_u)[(size_t)r * 128 + h * 32 + lane] = u;
    if (t == 0) d_flag[r] = (end > start) ? 1.0f : 0.0f;
}

// ---------------- K4: fused epilogue: pooled -> O -> rFF -> h = O@Wg^T ----------------
__global__ void k_epilogue(const float* __restrict__ Wv, const float* __restrict__ bv,
                           const float* __restrict__ Wo, const float* __restrict__ bo,
                           const float* __restrict__ Wg, int rpb) {
    extern __shared__ float sm[];
    float* Wv_s = sm;
    float* Wo_s = Wv_s + DIM * WPITCH;
    float* Wg_s = Wo_s + DIM * WPITCH;
    float* u_s  = Wg_s + DIM * WPITCH;   // 512
    float* O_s  = u_s + NHEAD * DIM;     // 128
    float* O2_s = O_s + DIM;             // 128
    int t = threadIdx.x;
    for (int idx = t; idx < DIM * DIM / 4; idx += blockDim.x) {
        int row = idx >> 5, col4 = idx & 31;
        float4 v0 = ((const float4*)Wv)[idx];
        float4 v1 = ((const float4*)Wo)[idx];
        float4 v2 = ((const float4*)Wg)[idx];
        *(float4*)(Wv_s + row * WPITCH + col4 * 4) = v0;
        *(float4*)(Wo_s + row * WPITCH + col4 * 4) = v1;
        *(float4*)(Wg_s + row * WPITCH + col4 * 4) = v2;
    }
    int h = t >> 5;
    float qv = d_q[t], bvv = bv[t], bov = bo[t];
    for (int k = 0; k < rpb; k++) {
        int r = blockIdx.x * rpb + k;
        if (r >= R_REG) break;
        __syncthreads();
        for (int idx = t; idx < NHEAD * DIM / 4; idx += blockDim.x)
            ((float4*)u_s)[idx] = ((const float4*)d_u)[(size_t)r * 128 + idx];
        float flag = d_flag[r];
        __syncthreads();
        // stage 1: pooled[j] = Wv[j,:].u_h + flag*bv[j];  O = q + pooled
        {
            const float4* wr = (const float4*)(Wv_s + t * WPITCH);
            const float4* uh = (const float4*)(u_s + h * DIM);
            float acc[4] = {0.f, 0.f, 0.f, 0.f};
            #pragma unroll
            for (int i = 0; i < DIM / 4; i++) {
                float4 w = wr[i]; float4 uu = uh[i];
                float a = acc[i & 3];
                a = fmaf(w.x, uu.x, a); a = fmaf(w.y, uu.y, a);
                a = fmaf(w.z, uu.z, a); a = fmaf(w.w, uu.w, a);
                acc[i & 3] = a;
            }
            O_s[t] = qv + (acc[0] + acc[1]) + (acc[2] + acc[3]) + flag * bvv;
        }
        __syncthreads();
        // stage 2: O2 = O + relu(Wo O + bo)
        {
            const float4* wr = (const float4*)(Wo_s + t * WPITCH);
            const float4* ov = (const float4*)O_s;
            float acc[4] = {bov, 0.f, 0.f, 0.f};
            #pragma unroll
            for (int i = 0; i < DIM / 4; i++) {
                float4 w = wr[i]; float4 o = ov[i];
                float a = acc[i & 3];
                a = fmaf(w.x, o.x, a); a = fmaf(w.y, o.y, a);
                a = fmaf(w.z, o.z, a); a = fmaf(w.w, o.w, a);
                acc[i & 3] = a;
            }
            O2_s[t] = O_s[t] + fmaxf((acc[0] + acc[1]) + (acc[2] + acc[3]), 0.f);
        }
        __syncthreads();
        // stage 3: h = Wg O2  -> global
        {
            const float4* wr = (const float4*)(Wg_s + t * WPITCH);
            const float4* ov = (const float4*)O2_s;
            float acc[4] = {0.f, 0.f, 0.f, 0.f};
            #pragma unroll
            for (int i = 0; i < DIM / 4; i++) {
                float4 w = wr[i]; float4 o = ov[i];
                float a = acc[i & 3];
                a = fmaf(w.x, o.x, a); a = fmaf(w.y, o.y, a);
                a = fmaf(w.z, o.z, a); a = fmaf(w.w, o.w, a);
                acc[i & 3] = a;
            }
            d_hbuf[(size_t)r * DIM + t] = (acc[0] + acc[1]) + (acc[2] + acc[3]);
        }
    }
}

// ---------------- K5: edge scatter out[dst] += norm * h[src] (warp per edge) ----------------
__global__ void k_edge(const int* __restrict__ adj, int E, float* __restrict__ out) {
    int widx = (blockIdx.x * blockDim.x + threadIdx.x) >> 5;
    int lane = threadIdx.x & 31;
    if (widx >= E) return;
    int s = adj[widx], d = adj[E + widx];
    float norm = rsqrtf(fmaxf(d_deg[s], 1e-12f)) * rsqrtf(fmaxf(d_deg[d], 1e-12f));
    const float* hr = d_hbuf + (size_t)s * DIM;
    float* orow = out + (size_t)d * DIM;
    #pragma unroll
    for (int j = lane; j < DIM; j += 32)
        atomicAdd(&orow[j], norm * hr[j]);
}

// ---------------- K6: self loop + PReLU ----------------
__global__ void k_final(const float* __restrict__ prelu, float* __restrict__ out) {
    int idx = blockIdx.x * blockDim.x + threadIdx.x;
    if (idx >= R_REG * DIM) return;
    int r = idx >> 7, j = idx & 127;
    float dis = rsqrtf(fmaxf(d_deg[r], 1e-12f));
    float val = out[idx] + dis * dis * d_hbuf[idx];
    out[idx] = val > 0.f ? val : prelu[j] * val;
}

// ---------------- launch ----------------
extern "C" void kernel_launch(void* const* d_in, const int* in_sizes, int n_in,
                              void* d_out, int out_size) {
    const float* x    = (const float*)d_in[0];
    const int*   zone = (const int*)d_in[1];
    const int*   adj  = (const int*)d_in[2];
    const float* S    = (const float*)d_in[3];
    const float* Wq   = (const float*)d_in[4];
    const float* bq   = (const float*)d_in[5];
    const float* Wk   = (const float*)d_in[6];
    const float* bk   = (const float*)d_in[7];
    const float* Wv   = (const float*)d_in[8];
    const float* bv   = (const float*)d_in[9];
    const float* Wo   = (const float*)d_in[10];
    const float* bo   = (const float*)d_in[11];
    const float* Wg   = (const float*)d_in[12];
    const float* bg   = (const float*)d_in[13];
    const float* prelu = (const float*)d_in[14];
    float* out = (float*)d_out;
    int N = in_sizes[0] / DIM;
    int E = in_sizes[2] / 2;

    // K0: init + histogram + setup
    int nbI = (R_REG * DIM + 255) / 256;
    int nbH = (N + HIST_CHUNK - 1) / HIST_CHUNK;
    k_init_setup<<<nbI + nbH + 1, 256>>>(bg, out, S, Wq, bq, Wk, bk, zone, N, nbI, nbH);

    // K1: scan (also resets d_hist for next graph replay)
    k_scan<<<1, 256>>>();

    // K2: scores -> sorted (order, esort), plus deg blocks.  8 warps/block, 4 pts/warp
    int nbS = (N + 31) / 32;
    int nbD = (E + 255) / 256;
    k_scores<<<nbS + nbD, 256>>>(x, zone, adj, N, E, nbS);

    // K3: per-region accumulation
    k_accum<<<R_REG, 128>>>(x);

    int smem_epi = (3 * DIM * WPITCH + NHEAD * DIM + 2 * DIM) * (int)sizeof(float);
    cudaFuncSetAttribute(k_epilogue, cudaFuncAttributeMaxDynamicSharedMemorySize, smem_epi);
    int rpb = 14;
    k_epilogue<<<(R_REG + rpb - 1) / rpb, 128, smem_epi>>>(Wv, bv, Wo, bo, Wg, rpb);

    k_edge<<<(E * 32 + 255) / 256, 256>>>(adj, E, out);
    k_final<<<(R_REG * DIM + 255) / 256, 256>>>(prelu, out);
}

// round 8
// speedup vs baseline: 1.2140x; 1.2140x over previous
#include <cuda_runtime.h>
#include <math.h>

#define R_REG 2000
#define NHEAD 4
#define DIM   128
#define DH    32
#define NMAX  500000
#define WPITCH 132   // smem pitch (floats) for conflict-free float4 matvec reads
#define HIST_CHUNK 8192

// ---------------- scratch (device globals; no allocation allowed) ----------------
__device__ float d_q[DIM];                      // PMA seed query (flattened)
__device__ float d_A[NHEAD * DIM];              // folded score matrix (incl 1/sqrt(D))
__device__ float d_c[NHEAD];                    // folded score bias
__device__ int   d_hist[R_REG];                 // zeroed by k_scan after reading (replay-safe)
__device__ int   d_starts[R_REG + 1];
__device__ int   d_cursor[R_REG];
__device__ int   d_order[NMAX];                 // point index, sorted by zone
__device__ __align__(16) float d_u[R_REG * NHEAD * DIM];  // normalized weighted sums of x
__device__ float d_flag[R_REG];                 // 1 if region nonempty
__device__ float d_hbuf[R_REG * DIM];           // GCN h = O @ Wg^T
__device__ float d_deg[R_REG];

// ---------------- K0: init + smem-privatized zone histogram + seed-query setup ----------------
__global__ void k_init_setup(const float* __restrict__ bg, float* __restrict__ out,
                             const float* __restrict__ S, const float* __restrict__ Wq,
                             const float* __restrict__ bq, const float* __restrict__ Wk,
                             const float* __restrict__ bk, const int* __restrict__ zone,
                             int N, int nbI, int nbH) {
    int t = threadIdx.x;
    int b = blockIdx.x;
    if (b < nbI) {
        int i = b * blockDim.x + t;
        if (i < R_REG * DIM) out[i] = bg[i & (DIM - 1)];
        if (i < R_REG) d_deg[i] = 1.0f;   // deg starts at 1 (self loop)
    } else if (b < nbI + nbH) {
        // privatized histogram: one smem pass per 8192 points, then sparse global flush
        __shared__ int hs[R_REG];
        for (int i = t; i < R_REG; i += 256) hs[i] = 0;
        __syncthreads();
        int base = (b - nbI) * HIST_CHUNK;
        int lim = min(HIST_CHUNK, N - base);
        for (int i = t; i < lim; i += 256) atomicAdd(&hs[zone[base + i]], 1);
        __syncthreads();
        for (int i = t; i < R_REG; i += 256) {
            int v = hs[i];
            if (v) atomicAdd(&d_hist[i], v);
        }
    } else {
        // ---- setup: q = Wq S + bq ; A = (q^T Wk)/sqrt(D) ----
        __shared__ float S_s[DIM];
        __shared__ float q_s[DIM];
        if (t < DIM) S_s[t] = S[t];
        __syncthreads();
        if (t < DIM) {
            float acc = bq[t];
            const float4* wrow = (const float4*)(Wq + t * DIM);
            const float4* s4 = (const float4*)S_s;
            #pragma unroll
            for (int i = 0; i < DIM / 4; i++) {
                float4 w = wrow[i]; float4 s = s4[i];
                acc = fmaf(w.x, s.x, acc); acc = fmaf(w.y, s.y, acc);
                acc = fmaf(w.z, s.z, acc); acc = fmaf(w.w, s.w, acc);
            }
            q_s[t] = acc;
            d_q[t] = acc;
        }
        __syncthreads();
        if (t < DIM) {
            const float invsq = 0.08838834764831845f;  // 1/sqrt(128)
            for (int h = 0; h < NHEAD; h++) {
                float a = 0.f;
                #pragma unroll 8
                for (int dh = 0; dh < DH; dh++)
                    a = fmaf(q_s[h * DH + dh], Wk[(h * DH + dh) * DIM + t], a);
                d_A[h * DIM + t] = a * invsq;
            }
            if (t < NHEAD) {
                float cc = 0.f;
                for (int dh = 0; dh < DH; dh++) cc = fmaf(q_s[t * DH + dh], bk[t * DH + dh], cc);
                d_c[t] = cc * invsq;
            }
        }
    }
}

// ---------------- K1: exclusive scan of histogram (single block); resets hist for next replay ----------------
__global__ void k_scan() {
    __shared__ int wsum[8];
    int t = threadIdx.x;                 // 256 threads, 8 elems each
    int base = t * 8;
    int vals[8]; int s = 0;
    #pragma unroll
    for (int i = 0; i < 8; i++) {
        int idx = base + i;
        int v = 0;
        if (idx < R_REG) { v = d_hist[idx]; d_hist[idx] = 0; }  // read + reset (replay-safe)
        vals[i] = s; s += v;
    }
    int lane = t & 31, w = t >> 5;
    int inc = s;
    #pragma unroll
    for (int off = 1; off < 32; off <<= 1) {
        int o = __shfl_up_sync(0xffffffffu, inc, off);
        if (lane >= off) inc += o;
    }
    if (lane == 31) wsum[w] = inc;
    __syncthreads();
    if (t == 0) {
        int acc = 0;
        for (int i = 0; i < 8; i++) { int v = wsum[i]; wsum[i] = acc; acc += v; }
        d_starts[R_REG] = acc;
    }
    __syncthreads();
    int texcl = inc - s + wsum[w];
    #pragma unroll
    for (int i = 0; i < 8; i++) {
        int idx = base + i;
        if (idx < R_REG) {
            int st = texcl + vals[i];
            d_starts[idx] = st;
            d_cursor[idx] = st;
        }
    }
}

// ---------------- K2: counting-sort scatter (4 pts/thread, int4 zone loads) + fused deg ----------------
__global__ void __launch_bounds__(256) k_sort(const int* __restrict__ zone,
                                              const int* __restrict__ adj,
                                              int N, int E, int nbS) {
    if ((int)blockIdx.x >= nbS) {
        int e = (blockIdx.x - nbS) * blockDim.x + threadIdx.x;
        if (e < E) atomicAdd(&d_deg[adj[E + e]], 1.0f);
        return;
    }
    int tid = blockIdx.x * blockDim.x + threadIdx.x;
    int base = tid * 4;
    if (base >= N) return;
    if (base + 3 < N) {
        int4 z = *(const int4*)(zone + base);   // 16B vector load
        // 4 independent atomic chains in flight
        int p0 = atomicAdd(&d_cursor[z.x], 1);
        int p1 = atomicAdd(&d_cursor[z.y], 1);
        int p2 = atomicAdd(&d_cursor[z.z], 1);
        int p3 = atomicAdd(&d_cursor[z.w], 1);
        d_order[p0] = base;
        d_order[p1] = base + 1;
        d_order[p2] = base + 2;
        d_order[p3] = base + 3;
    } else {
        for (int n = base; n < N; n++) {
            int pos = atomicAdd(&d_cursor[zone[n]], 1);
            d_order[pos] = n;
        }
    }
}

// 4-head warp reduction in 9 shfls; lanes 0,8,16,24 return full sums for heads 0..3
__device__ __forceinline__ float headred(float s0, float s1, float s2, float s3, int lane) {
    float o0 = __shfl_xor_sync(0xffffffffu, s0, 16);
    float o1 = __shfl_xor_sync(0xffffffffu, s1, 16);
    float o2 = __shfl_xor_sync(0xffffffffu, s2, 16);
    float o3 = __shfl_xor_sync(0xffffffffu, s3, 16);
    float t0, t1;
    if (lane < 16) { t0 = s0 + o0; t1 = s1 + o1; } else { t0 = s2 + o2; t1 = s3 + o3; }
    float p0 = __shfl_xor_sync(0xffffffffu, t0, 8);
    float p1 = __shfl_xor_sync(0xffffffffu, t1, 8);
    float v = ((lane & 8) == 0) ? (t0 + p0) : (t1 + p1);
    v += __shfl_xor_sync(0xffffffffu, v, 4);
    v += __shfl_xor_sync(0xffffffffu, v, 2);
    v += __shfl_xor_sync(0xffffffffu, v, 1);
    return v;
}

// ---------------- K3: single-pass score + weighted accumulation (x read ONCE) ----------------
// Per gathered x row: dot with resident A regs -> warp-reduce -> exp (1 MUFU-chain/lane)
// -> broadcast e -> FMA accumulate. Softmax normalization deferred to the end (sum of e).
__global__ void __launch_bounds__(128) k_accum(const float* __restrict__ x) {
    int r = blockIdx.x;
    int t = threadIdx.x;
    int w = t >> 5, lane = t & 31;
    int start = d_starts[r], end = d_starts[r + 1];
    const float4* x4 = (const float4*)x;
    const float4* A4 = (const float4*)d_A;
    float4 A0 = A4[0 * 32 + lane], A1 = A4[1 * 32 + lane];
    float4 A2 = A4[2 * 32 + lane], A3 = A4[3 * 32 + lane];
    float cb = d_c[lane >> 3];   // correct bias on lanes 0,8,16,24 (head = lane>>3)
    float4 a0 = make_float4(0.f,0.f,0.f,0.f), a1 = a0, a2 = a0, a3 = a0;
    float dn0 = 0.f, dn1 = 0.f, dn2 = 0.f, dn3 = 0.f;
    #define DOT4(a, v) ((a).x*(v).x + (a).y*(v).y + (a).z*(v).z + (a).w*(v).w)
    // warp w handles points {start+2w, start+2w+1}, stride 8 -> 2 indep gathers/iter
    #pragma unroll 2
    for (int p = start + 2 * w; p < end; p += 8) {
        bool h1 = (p + 1 < end);
        int n0 = __ldg(&d_order[p]);
        int n1 = h1 ? __ldg(&d_order[p + 1]) : n0;     // dup gather on tail; e1 forced 0
        float4 xv0 = __ldg(&x4[(size_t)n0 * 32 + lane]);
        float4 xv1 = __ldg(&x4[(size_t)n1 * 32 + lane]);
        // inline scores for both points (ILP across the two reduction trees)
        float v0 = headred(DOT4(A0,xv0), DOT4(A1,xv0), DOT4(A2,xv0), DOT4(A3,xv0), lane);
        float v1 = headred(DOT4(A0,xv1), DOT4(A1,xv1), DOT4(A2,xv1), DOT4(A3,xv1), lane);
        // one expf per lane per point; results broadcast from lanes 0,8,16,24
        float ev0 = expf(v0 + cb);
        float ev1 = expf(v1 + cb);
        float e00 = __shfl_sync(0xffffffffu, ev0, 0);
        float e01 = __shfl_sync(0xffffffffu, ev0, 8);
        float e02 = __shfl_sync(0xffffffffu, ev0, 16);
        float e03 = __shfl_sync(0xffffffffu, ev0, 24);
        float e10 = __shfl_sync(0xffffffffu, ev1, 0);
        float e11 = __shfl_sync(0xffffffffu, ev1, 8);
        float e12 = __shfl_sync(0xffffffffu, ev1, 16);
        float e13 = __shfl_sync(0xffffffffu, ev1, 24);
        if (!h1) { e10 = e11 = e12 = e13 = 0.f; }
        a0.x = fmaf(e00, xv0.x, a0.x); a0.y = fmaf(e00, xv0.y, a0.y);
        a0.z = fmaf(e00, xv0.z, a0.z); a0.w = fmaf(e00, xv0.w, a0.w);
        a1.x = fmaf(e01, xv0.x, a1.x); a1.y = fmaf(e01, xv0.y, a1.y);
        a1.z = fmaf(e01, xv0.z, a1.z); a1.w = fmaf(e01, xv0.w, a1.w);
        a2.x = fmaf(e02, xv0.x, a2.x); a2.y = fmaf(e02, xv0.y, a2.y);
        a2.z = fmaf(e02, xv0.z, a2.z); a2.w = fmaf(e02, xv0.w, a2.w);
        a3.x = fmaf(e03, xv0.x, a3.x); a3.y = fmaf(e03, xv0.y, a3.y);
        a3.z = fmaf(e03, xv0.z, a3.z); a3.w = fmaf(e03, xv0.w, a3.w);
        dn0 += e00; dn1 += e01; dn2 += e02; dn3 += e03;
        a0.x = fmaf(e10, xv1.x, a0.x); a0.y = fmaf(e10, xv1.y, a0.y);
        a0.z = fmaf(e10, xv1.z, a0.z); a0.w = fmaf(e10, xv1.w, a0.w);
        a1.x = fmaf(e11, xv1.x, a1.x); a1.y = fmaf(e11, xv1.y, a1.y);
        a1.z = fmaf(e11, xv1.z, a1.z); a1.w = fmaf(e11, xv1.w, a1.w);
        a2.x = fmaf(e12, xv1.x, a2.x); a2.y = fmaf(e12, xv1.y, a2.y);
        a2.z = fmaf(e12, xv1.z, a2.z); a2.w = fmaf(e12, xv1.w, a2.w);
        a3.x = fmaf(e13, xv1.x, a3.x); a3.y = fmaf(e13, xv1.y, a3.y);
        a3.z = fmaf(e13, xv1.z, a3.z); a3.w = fmaf(e13, xv1.w, a3.w);
        dn0 += e10; dn1 += e11; dn2 += e12; dn3 += e13;
    }
    #undef DOT4
    // cross-warp combine in smem: part[warp][head][lane] (float4 = dims 4*lane..4*lane+3)
    __shared__ float4 part[4][4][32];
    __shared__ float pdn[4][4];
    part[w][0][lane] = a0; part[w][1][lane] = a1;
    part[w][2][lane] = a2; part[w][3][lane] = a3;
    if (lane == 0) { pdn[w][0] = dn0; pdn[w][1] = dn1; pdn[w][2] = dn2; pdn[w][3] = dn3; }
    __syncthreads();
    // thread t = (h=w, lane) finalizes head w
    int h = w;
    float4 s0 = part[0][h][lane], s1 = part[1][h][lane];
    float4 s2 = part[2][h][lane], s3 = part[3][h][lane];
    float4 u;
    u.x = s0.x + s1.x + s2.x + s3.x;
    u.y = s0.y + s1.y + s2.y + s3.y;
    u.z = s0.z + s1.z + s2.z + s3.z;
    u.w = s0.w + s1.w + s2.w + s3.w;
    float dn = pdn[0][h] + pdn[1][h] + pdn[2][h] + pdn[3][h];
    float inv = dn > 0.f ? 1.0f / dn : 0.f;
    u.x *= inv; u.y *= inv; u.z *= inv; u.w *= inv;
    ((float4*)d_u)[(size_t)r * 128 + h * 32 + lane] = u;
    if (t == 0) d_flag[r] = (end > start) ? 1.0f : 0.0f;
}

// ---------------- K4: fused epilogue: pooled -> O -> rFF -> h = O@Wg^T ----------------
__global__ void k_epilogue(const float* __restrict__ Wv, const float* __restrict__ bv,
                           const float* __restrict__ Wo, const float* __restrict__ bo,
                           const float* __restrict__ Wg, int rpb) {
    extern __shared__ float sm[];
    float* Wv_s = sm;
    float* Wo_s = Wv_s + DIM * WPITCH;
    float* Wg_s = Wo_s + DIM * WPITCH;
    float* u_s  = Wg_s + DIM * WPITCH;   // 512
    float* O_s  = u_s + NHEAD * DIM;     // 128
    float* O2_s = O_s + DIM;             // 128
    int t = threadIdx.x;
    for (int idx = t; idx < DIM * DIM / 4; idx += blockDim.x) {
        int row = idx >> 5, col4 = idx & 31;
        float4 v0 = ((const float4*)Wv)[idx];
        float4 v1 = ((const float4*)Wo)[idx];
        float4 v2 = ((const float4*)Wg)[idx];
        *(float4*)(Wv_s + row * WPITCH + col4 * 4) = v0;
        *(float4*)(Wo_s + row * WPITCH + col4 * 4) = v1;
        *(float4*)(Wg_s + row * WPITCH + col4 * 4) = v2;
    }
    int h = t >> 5;
    float qv = d_q[t], bvv = bv[t], bov = bo[t];
    for (int k = 0; k < rpb; k++) {
        int r = blockIdx.x * rpb + k;
        if (r >= R_REG) break;
        __syncthreads();
        for (int idx = t; idx < NHEAD * DIM / 4; idx += blockDim.x)
            ((float4*)u_s)[idx] = ((const float4*)d_u)[(size_t)r * 128 + idx];
        float flag = d_flag[r];
        __syncthreads();
        // stage 1: pooled[j] = Wv[j,:].u_h + flag*bv[j];  O = q + pooled
        {
            const float4* wr = (const float4*)(Wv_s + t * WPITCH);
            const float4* uh = (const float4*)(u_s + h * DIM);
            float acc[4] = {0.f, 0.f, 0.f, 0.f};
            #pragma unroll
            for (int i = 0; i < DIM / 4; i++) {
                float4 w = wr[i]; float4 uu = uh[i];
                float a = acc[i & 3];
                a = fmaf(w.x, uu.x, a); a = fmaf(w.y, uu.y, a);
                a = fmaf(w.z, uu.z, a); a = fmaf(w.w, uu.w, a);
                acc[i & 3] = a;
            }
            O_s[t] = qv + (acc[0] + acc[1]) + (acc[2] + acc[3]) + flag * bvv;
        }
        __syncthreads();
        // stage 2: O2 = O + relu(Wo O + bo)
        {
            const float4* wr = (const float4*)(Wo_s + t * WPITCH);
            const float4* ov = (const float4*)O_s;
            float acc[4] = {bov, 0.f, 0.f, 0.f};
            #pragma unroll
            for (int i = 0; i < DIM / 4; i++) {
                float4 w = wr[i]; float4 o = ov[i];
                float a = acc[i & 3];
                a = fmaf(w.x, o.x, a); a = fmaf(w.y, o.y, a);
                a = fmaf(w.z, o.z, a); a = fmaf(w.w, o.w, a);
                acc[i & 3] = a;
            }
            O2_s[t] = O_s[t] + fmaxf((acc[0] + acc[1]) + (acc[2] + acc[3]), 0.f);
        }
        __syncthreads();
        // stage 3: h = Wg O2  -> global
        {
            const float4* wr = (const float4*)(Wg_s + t * WPITCH);
            const float4* ov = (const float4*)O2_s;
            float acc[4] = {0.f, 0.f, 0.f, 0.f};
            #pragma unroll
            for (int i = 0; i < DIM / 4; i++) {
                float4 w = wr[i]; float4 o = ov[i];
                float a = acc[i & 3];
                a = fmaf(w.x, o.x, a); a = fmaf(w.y, o.y, a);
                a = fmaf(w.z, o.z, a); a = fmaf(w.w, o.w, a);
                acc[i & 3] = a;
            }
            d_hbuf[(size_t)r * DIM + t] = (acc[0] + acc[1]) + (acc[2] + acc[3]);
        }
    }
}

// ---------------- K5: edge scatter out[dst] += norm * h[src] (warp per edge) ----------------
__global__ void k_edge(const int* __restrict__ adj, int E, float* __restrict__ out) {
    int widx = (blockIdx.x * blockDim.x + threadIdx.x) >> 5;
    int lane = threadIdx.x & 31;
    if (widx >= E) return;
    int s = adj[widx], d = adj[E + widx];
    float norm = rsqrtf(fmaxf(d_deg[s], 1e-12f)) * rsqrtf(fmaxf(d_deg[d], 1e-12f));
    const float* hr = d_hbuf + (size_t)s * DIM;
    float* orow = out + (size_t)d * DIM;
    #pragma unroll
    for (int j = lane; j < DIM; j += 32)
        atomicAdd(&orow[j], norm * hr[j]);
}

// ---------------- K6: self loop + PReLU ----------------
__global__ void k_final(const float* __restrict__ prelu, float* __restrict__ out) {
    int idx = blockIdx.x * blockDim.x + threadIdx.x;
    if (idx >= R_REG * DIM) return;
    int r = idx >> 7, j = idx & 127;
    float dis = rsqrtf(fmaxf(d_deg[r], 1e-12f));
    float val = out[idx] + dis * dis * d_hbuf[idx];
    out[idx] = val > 0.f ? val : prelu[j] * val;
}

// ---------------- launch ----------------
extern "C" void kernel_launch(void* const* d_in, const int* in_sizes, int n_in,
                              void* d_out, int out_size) {
    const float* x    = (const float*)d_in[0];
    const int*   zone = (const int*)d_in[1];
    const int*   adj  = (const int*)d_in[2];
    const float* S    = (const float*)d_in[3];
    const float* Wq   = (const float*)d_in[4];
    const float* bq   = (const float*)d_in[5];
    const float* Wk   = (const float*)d_in[6];
    const float* bk   = (const float*)d_in[7];
    const float* Wv   = (const float*)d_in[8];
    const float* bv   = (const float*)d_in[9];
    const float* Wo   = (const float*)d_in[10];
    const float* bo   = (const float*)d_in[11];
    const float* Wg   = (const float*)d_in[12];
    const float* bg   = (const float*)d_in[13];
    const float* prelu = (const float*)d_in[14];
    float* out = (float*)d_out;
    int N = in_sizes[0] / DIM;
    int E = in_sizes[2] / 2;

    // K0: init + histogram + setup
    int nbI = (R_REG * DIM + 255) / 256;
    int nbH = (N + HIST_CHUNK - 1) / HIST_CHUNK;
    k_init_setup<<<nbI + nbH + 1, 256>>>(bg, out, S, Wq, bq, Wk, bk, zone, N, nbI, nbH);

    // K1: scan (also resets d_hist for next graph replay)
    k_scan<<<1, 256>>>();

    // K2: counting-sort scatter (4 pts/thread) + deg blocks
    int nbS = (N + 1023) / 1024;
    int nbD = (E + 255) / 256;
    k_sort<<<nbS + nbD, 256>>>(zone, adj, N, E, nbS);

    // K3: fused score+accumulate — single pass over x
    k_accum<<<R_REG, 128>>>(x);

    int smem_epi = (3 * DIM * WPITCH + NHEAD * DIM + 2 * DIM) * (int)sizeof(float);
    cudaFuncSetAttribute(k_epilogue, cudaFuncAttributeMaxDynamicSharedMemorySize, smem_epi);
    int rpb = 14;
    k_epilogue<<<(R_REG + rpb - 1) / rpb, 128, smem_epi>>>(Wv, bv, Wo, bo, Wg, rpb);

    k_edge<<<(E * 32 + 255) / 256, 256>>>(adj, E, out);
    k_final<<<(R_REG * DIM + 255) / 256, 256>>>(prelu, out);
}

// round 9
// speedup vs baseline: 1.2759x; 1.0510x over previous
#include <cuda_runtime.h>
#include <math.h>

#define R_REG 2000
#define NHEAD 4
#define DIM   128
#define DH    32
#define NMAX  500000
#define WPITCH 132   // smem pitch (floats) for conflict-free float4 matvec reads
#define HIST_CHUNK 16384

// ---------------- scratch (device globals; no allocation allowed) ----------------
__device__ float d_q[DIM];                      // PMA seed query (flattened)
__device__ float d_A[NHEAD * DIM];              // folded score matrix (incl 1/sqrt(D))
__device__ float d_c[NHEAD];                    // folded score bias
__device__ int   d_hist[R_REG];                 // zeroed by k_scan after reading (replay-safe)
__device__ int   d_starts[R_REG + 1];
__device__ int   d_cursor[R_REG];
__device__ int   d_order[NMAX];                 // point index, sorted by zone
__device__ __align__(16) float d_u[R_REG * NHEAD * DIM];  // normalized weighted sums of x
__device__ float d_flag[R_REG];                 // 1 if region nonempty
__device__ float d_hbuf[R_REG * DIM];           // GCN h = O @ Wg^T
__device__ float d_deg[R_REG];

// ---------------- K0: init + smem-privatized zone histogram + seed-query setup ----------------
__global__ void k_init_setup(const float* __restrict__ bg, float* __restrict__ out,
                             const float* __restrict__ S, const float* __restrict__ Wq,
                             const float* __restrict__ bq, const float* __restrict__ Wk,
                             const float* __restrict__ bk, const int* __restrict__ zone,
                             int N, int nbI, int nbH) {
    int t = threadIdx.x;
    int b = blockIdx.x;
    if (b < nbI) {
        int i = b * blockDim.x + t;
        if (i < R_REG * DIM) out[i] = bg[i & (DIM - 1)];
        if (i < R_REG) d_deg[i] = 1.0f;   // deg starts at 1 (self loop)
    } else if (b < nbI + nbH) {
        // privatized histogram: one smem pass per chunk, then sparse global flush
        __shared__ int hs[R_REG];
        for (int i = t; i < R_REG; i += 256) hs[i] = 0;
        __syncthreads();
        int base = (b - nbI) * HIST_CHUNK;
        int lim = min(HIST_CHUNK, N - base);
        for (int i = t; i < lim; i += 256) atomicAdd(&hs[zone[base + i]], 1);
        __syncthreads();
        for (int i = t; i < R_REG; i += 256) {
            int v = hs[i];
            if (v) atomicAdd(&d_hist[i], v);
        }
    } else {
        // ---- setup: q = Wq S + bq ; A = (q^T Wk)/sqrt(D) ----
        __shared__ float S_s[DIM];
        __shared__ float q_s[DIM];
        if (t < DIM) S_s[t] = S[t];
        __syncthreads();
        if (t < DIM) {
            float acc = bq[t];
            const float4* wrow = (const float4*)(Wq + t * DIM);
            const float4* s4 = (const float4*)S_s;
            #pragma unroll
            for (int i = 0; i < DIM / 4; i++) {
                float4 w = wrow[i]; float4 s = s4[i];
                acc = fmaf(w.x, s.x, acc); acc = fmaf(w.y, s.y, acc);
                acc = fmaf(w.z, s.z, acc); acc = fmaf(w.w, s.w, acc);
            }
            q_s[t] = acc;
            d_q[t] = acc;
        }
        __syncthreads();
        if (t < DIM) {
            const float invsq = 0.08838834764831845f;  // 1/sqrt(128)
            for (int h = 0; h < NHEAD; h++) {
                float a = 0.f;
                #pragma unroll 8
                for (int dh = 0; dh < DH; dh++)
                    a = fmaf(q_s[h * DH + dh], Wk[(h * DH + dh) * DIM + t], a);
                d_A[h * DIM + t] = a * invsq;
            }
            if (t < NHEAD) {
                float cc = 0.f;
                for (int dh = 0; dh < DH; dh++) cc = fmaf(q_s[t * DH + dh], bk[t * DH + dh], cc);
                d_c[t] = cc * invsq;
            }
        }
    }
}

// ---------------- K1: exclusive scan of histogram (single block); resets hist for next replay ----------------
__global__ void k_scan() {
    __shared__ int wsum[8];
    int t = threadIdx.x;                 // 256 threads, 8 elems each
    int base = t * 8;
    int vals[8]; int s = 0;
    #pragma unroll
    for (int i = 0; i < 8; i++) {
        int idx = base + i;
        int v = 0;
        if (idx < R_REG) { v = d_hist[idx]; d_hist[idx] = 0; }  // read + reset (replay-safe)
        vals[i] = s; s += v;
    }
    int lane = t & 31, w = t >> 5;
    int inc = s;
    #pragma unroll
    for (int off = 1; off < 32; off <<= 1) {
        int o = __shfl_up_sync(0xffffffffu, inc, off);
        if (lane >= off) inc += o;
    }
    if (lane == 31) wsum[w] = inc;
    __syncthreads();
    if (t == 0) {
        int acc = 0;
        for (int i = 0; i < 8; i++) { int v = wsum[i]; wsum[i] = acc; acc += v; }
        d_starts[R_REG] = acc;
    }
    __syncthreads();
    int texcl = inc - s + wsum[w];
    #pragma unroll
    for (int i = 0; i < 8; i++) {
        int idx = base + i;
        if (idx < R_REG) {
            int st = texcl + vals[i];
            d_starts[idx] = st;
            d_cursor[idx] = st;
        }
    }
}

// ---------------- K2: counting-sort scatter (4 pts/thread, int4 zone loads) + fused deg ----------------
__global__ void __launch_bounds__(256) k_sort(const int* __restrict__ zone,
                                              const int* __restrict__ adj,
                                              int N, int E, int nbS) {
    if ((int)blockIdx.x >= nbS) {
        int e = (blockIdx.x - nbS) * blockDim.x + threadIdx.x;
        if (e < E) atomicAdd(&d_deg[adj[E + e]], 1.0f);
        return;
    }
    int tid = blockIdx.x * blockDim.x + threadIdx.x;
    int base = tid * 4;
    if (base >= N) return;
    if (base + 3 < N) {
        int4 z = *(const int4*)(zone + base);   // 16B vector load
        // 4 independent atomic chains in flight
        int p0 = atomicAdd(&d_cursor[z.x], 1);
        int p1 = atomicAdd(&d_cursor[z.y], 1);
        int p2 = atomicAdd(&d_cursor[z.z], 1);
        int p3 = atomicAdd(&d_cursor[z.w], 1);
        d_order[p0] = base;
        d_order[p1] = base + 1;
        d_order[p2] = base + 2;
        d_order[p3] = base + 3;
    } else {
        for (int n = base; n < N; n++) {
            int pos = atomicAdd(&d_cursor[zone[n]], 1);
            d_order[pos] = n;
        }
    }
}

// 4-head warp reduction in 9 shfls; lanes 0,8,16,24 return full sums for heads 0..3
__device__ __forceinline__ float headred(float s0, float s1, float s2, float s3, int lane) {
    float o0 = __shfl_xor_sync(0xffffffffu, s0, 16);
    float o1 = __shfl_xor_sync(0xffffffffu, s1, 16);
    float o2 = __shfl_xor_sync(0xffffffffu, s2, 16);
    float o3 = __shfl_xor_sync(0xffffffffu, s3, 16);
    float t0, t1;
    if (lane < 16) { t0 = s0 + o0; t1 = s1 + o1; } else { t0 = s2 + o2; t1 = s3 + o3; }
    float p0 = __shfl_xor_sync(0xffffffffu, t0, 8);
    float p1 = __shfl_xor_sync(0xffffffffu, t1, 8);
    float v = ((lane & 8) == 0) ? (t0 + p0) : (t1 + p1);
    v += __shfl_xor_sync(0xffffffffu, v, 4);
    v += __shfl_xor_sync(0xffffffffu, v, 2);
    v += __shfl_xor_sync(0xffffffffu, v, 1);
    return v;
}

// ---------------- K3: single-pass score + weighted accumulation (x read ONCE) ----------------
// ILP-4 per warp + software-pipelined order prefetch: next iteration's indices are
// loaded while the current x-rows are in flight, so the steady-state chain is only
// x-load -> dot/shfl-tree -> exp -> FMA.  4 independent 512B gathers per warp per iter.
__global__ void __launch_bounds__(128) k_accum(const float* __restrict__ x) {
    int r = blockIdx.x;
    int t = threadIdx.x;
    int w = t >> 5, lane = t & 31;
    int start = d_starts[r], end = d_starts[r + 1];
    const float4* x4 = (const float4*)x;
    const float4* A4 = (const float4*)d_A;
    float4 A0 = A4[0 * 32 + lane], A1 = A4[1 * 32 + lane];
    float4 A2 = A4[2 * 32 + lane], A3 = A4[3 * 32 + lane];
    float cb = d_c[lane >> 3];   // head bias on lanes 0,8,16,24 (head = lane>>3)
    float4 a0 = make_float4(0.f,0.f,0.f,0.f), a1 = a0, a2 = a0, a3 = a0;
    float dn0 = 0.f, dn1 = 0.f, dn2 = 0.f, dn3 = 0.f;
    #define DOT4(a, v) ((a).x*(v).x + (a).y*(v).y + (a).z*(v).z + (a).w*(v).w)
    int p = start + 4 * w;
    int n0 = 0, n1 = 0, n2 = 0, n3 = 0;
    if (p < end) {
        n0 = __ldg(&d_order[p]);
        n1 = (p + 1 < end) ? __ldg(&d_order[p + 1]) : n0;
        n2 = (p + 2 < end) ? __ldg(&d_order[p + 2]) : n0;
        n3 = (p + 3 < end) ? __ldg(&d_order[p + 3]) : n0;
    }
    #pragma unroll 1
    while (p < end) {
        int rem = end - p;
        // 4 independent x-row gathers (2KB in flight per warp)
        float4 xv0 = __ldg(&x4[(size_t)n0 * 32 + lane]);
        float4 xv1 = __ldg(&x4[(size_t)n1 * 32 + lane]);
        float4 xv2 = __ldg(&x4[(size_t)n2 * 32 + lane]);
        float4 xv3 = __ldg(&x4[(size_t)n3 * 32 + lane]);
        // prefetch next iteration's order indices (off the critical chain)
        int pn = p + 16;
        if (pn < end) {
            n0 = __ldg(&d_order[pn]);
            n1 = (pn + 1 < end) ? __ldg(&d_order[pn + 1]) : n0;
            n2 = (pn + 2 < end) ? __ldg(&d_order[pn + 2]) : n0;
            n3 = (pn + 3 < end) ? __ldg(&d_order[pn + 3]) : n0;
        }
        // 4 interleaved score reductions (shfl latencies hide each other)
        float v0 = headred(DOT4(A0,xv0), DOT4(A1,xv0), DOT4(A2,xv0), DOT4(A3,xv0), lane);
        float v1 = headred(DOT4(A0,xv1), DOT4(A1,xv1), DOT4(A2,xv1), DOT4(A3,xv1), lane);
        float v2 = headred(DOT4(A0,xv2), DOT4(A1,xv2), DOT4(A2,xv2), DOT4(A3,xv2), lane);
        float v3 = headred(DOT4(A0,xv3), DOT4(A1,xv3), DOT4(A2,xv3), DOT4(A3,xv3), lane);
        float ev0 = expf(v0 + cb);
        float ev1 = expf(v1 + cb);
        float ev2 = expf(v2 + cb);
        float ev3 = expf(v3 + cb);
        float e00 = __shfl_sync(0xffffffffu, ev0, 0);
        float e01 = __shfl_sync(0xffffffffu, ev0, 8);
        float e02 = __shfl_sync(0xffffffffu, ev0, 16);
        float e03 = __shfl_sync(0xffffffffu, ev0, 24);
        float e10 = __shfl_sync(0xffffffffu, ev1, 0);
        float e11 = __shfl_sync(0xffffffffu, ev1, 8);
        float e12 = __shfl_sync(0xffffffffu, ev1, 16);
        float e13 = __shfl_sync(0xffffffffu, ev1, 24);
        float e20 = __shfl_sync(0xffffffffu, ev2, 0);
        float e21 = __shfl_sync(0xffffffffu, ev2, 8);
        float e22 = __shfl_sync(0xffffffffu, ev2, 16);
        float e23 = __shfl_sync(0xffffffffu, ev2, 24);
        float e30 = __shfl_sync(0xffffffffu, ev3, 0);
        float e31 = __shfl_sync(0xffffffffu, ev3, 8);
        float e32 = __shfl_sync(0xffffffffu, ev3, 16);
        float e33 = __shfl_sync(0xffffffffu, ev3, 24);
        if (rem < 4) {   // kill duplicated-tail contributions
            if (rem < 2) { e10 = e11 = e12 = e13 = 0.f; }
            if (rem < 3) { e20 = e21 = e22 = e23 = 0.f; }
            e30 = e31 = e32 = e33 = 0.f;
        }
        a0.x = fmaf(e00, xv0.x, a0.x); a0.y = fmaf(e00, xv0.y, a0.y);
        a0.z = fmaf(e00, xv0.z, a0.z); a0.w = fmaf(e00, xv0.w, a0.w);
        a1.x = fmaf(e01, xv0.x, a1.x); a1.y = fmaf(e01, xv0.y, a1.y);
        a1.z = fmaf(e01, xv0.z, a1.z); a1.w = fmaf(e01, xv0.w, a1.w);
        a2.x = fmaf(e02, xv0.x, a2.x); a2.y = fmaf(e02, xv0.y, a2.y);
        a2.z = fmaf(e02, xv0.z, a2.z); a2.w = fmaf(e02, xv0.w, a2.w);
        a3.x = fmaf(e03, xv0.x, a3.x); a3.y = fmaf(e03, xv0.y, a3.y);
        a3.z = fmaf(e03, xv0.z, a3.z); a3.w = fmaf(e03, xv0.w, a3.w);
        dn0 += e00; dn1 += e01; dn2 += e02; dn3 += e03;
        a0.x = fmaf(e10, xv1.x, a0.x); a0.y = fmaf(e10, xv1.y, a0.y);
        a0.z = fmaf(e10, xv1.z, a0.z); a0.w = fmaf(e10, xv1.w, a0.w);
        a1.x = fmaf(e11, xv1.x, a1.x); a1.y = fmaf(e11, xv1.y, a1.y);
        a1.z = fmaf(e11, xv1.z, a1.z); a1.w = fmaf(e11, xv1.w, a1.w);
        a2.x = fmaf(e12, xv1.x, a2.x); a2.y = fmaf(e12, xv1.y, a2.y);
        a2.z = fmaf(e12, xv1.z, a2.z); a2.w = fmaf(e12, xv1.w, a2.w);
        a3.x = fmaf(e13, xv1.x, a3.x); a3.y = fmaf(e13, xv1.y, a3.y);
        a3.z = fmaf(e13, xv1.z, a3.z); a3.w = fmaf(e13, xv1.w, a3.w);
        dn0 += e10; dn1 += e11; dn2 += e12; dn3 += e13;
        a0.x = fmaf(e20, xv2.x, a0.x); a0.y = fmaf(e20, xv2.y, a0.y);
        a0.z = fmaf(e20, xv2.z, a0.z); a0.w = fmaf(e20, xv2.w, a0.w);
        a1.x = fmaf(e21, xv2.x, a1.x); a1.y = fmaf(e21, xv2.y, a1.y);
        a1.z = fmaf(e21, xv2.z, a1.z); a1.w = fmaf(e21, xv2.w, a1.w);
        a2.x = fmaf(e22, xv2.x, a2.x); a2.y = fmaf(e22, xv2.y, a2.y);
        a2.z = fmaf(e22, xv2.z, a2.z); a2.w = fmaf(e22, xv2.w, a2.w);
        a3.x = fmaf(e23, xv2.x, a3.x); a3.y = fmaf(e23, xv2.y, a3.y);
        a3.z = fmaf(e23, xv2.z, a3.z); a3.w = fmaf(e23, xv2.w, a3.w);
        dn0 += e20; dn1 += e21; dn2 += e22; dn3 += e23;
        a0.x = fmaf(e30, xv3.x, a0.x); a0.y = fmaf(e30, xv3.y, a0.y);
        a0.z = fmaf(e30, xv3.z, a0.z); a0.w = fmaf(e30, xv3.w, a0.w);
        a1.x = fmaf(e31, xv3.x, a1.x); a1.y = fmaf(e31, xv3.y, a1.y);
        a1.z = fmaf(e31, xv3.z, a1.z); a1.w = fmaf(e31, xv3.w, a1.w);
        a2.x = fmaf(e32, xv3.x, a2.x); a2.y = fmaf(e32, xv3.y, a2.y);
        a2.z = fmaf(e32, xv3.z, a2.z); a2.w = fmaf(e32, xv3.w, a2.w);
        a3.x = fmaf(e33, xv3.x, a3.x); a3.y = fmaf(e33, xv3.y, a3.y);
        a3.z = fmaf(e33, xv3.z, a3.z); a3.w = fmaf(e33, xv3.w, a3.w);
        dn0 += e30; dn1 += e31; dn2 += e32; dn3 += e33;
        p = pn;
    }
    #undef DOT4
    // cross-warp combine in smem: part[warp][head][lane] (float4 = dims 4*lane..4*lane+3)
    __shared__ float4 part[4][4][32];
    __shared__ float pdn[4][4];
    part[w][0][lane] = a0; part[w][1][lane] = a1;
    part[w][2][lane] = a2; part[w][3][lane] = a3;
    if (lane == 0) { pdn[w][0] = dn0; pdn[w][1] = dn1; pdn[w][2] = dn2; pdn[w][3] = dn3; }
    __syncthreads();
    // thread t = (h=w, lane) finalizes head w
    int h = w;
    float4 s0 = part[0][h][lane], s1 = part[1][h][lane];
    float4 s2 = part[2][h][lane], s3 = part[3][h][lane];
    float4 u;
    u.x = s0.x + s1.x + s2.x + s3.x;
    u.y = s0.y + s1.y + s2.y + s3.y;
    u.z = s0.z + s1.z + s2.z + s3.z;
    u.w = s0.w + s1.w + s2.w + s3.w;
    float dn = pdn[0][h] + pdn[1][h] + pdn[2][h] + pdn[3][h];
    float inv = dn > 0.f ? 1.0f / dn : 0.f;
    u.x *= inv; u.y *= inv; u.z *= inv; u.w *= inv;
    ((float4*)d_u)[(size_t)r * 128 + h * 32 + lane] = u;
    if (t == 0) d_flag[r] = (end > start) ? 1.0f : 0.0f;
}

// ---------------- K4: fused epilogue: pooled -> O -> rFF -> h = O@Wg^T ----------------
__global__ void k_epilogue(const float* __restrict__ Wv, const float* __restrict__ bv,
                           const float* __restrict__ Wo, const float* __restrict__ bo,
                           const float* __restrict__ Wg, int rpb) {
    extern __shared__ float sm[];
    float* Wv_s = sm;
    float* Wo_s = Wv_s + DIM * WPITCH;
    float* Wg_s = Wo_s + DIM * WPITCH;
    float* u_s  = Wg_s + DIM * WPITCH;   // 512
    float* O_s  = u_s + NHEAD * DIM;     // 128
    float* O2_s = O_s + DIM;             // 128
    int t = threadIdx.x;
    for (int idx = t; idx < DIM * DIM / 4; idx += blockDim.x) {
        int row = idx >> 5, col4 = idx & 31;
        float4 v0 = ((const float4*)Wv)[idx];
        float4 v1 = ((const float4*)Wo)[idx];
        float4 v2 = ((const float4*)Wg)[idx];
        *(float4*)(Wv_s + row * WPITCH + col4 * 4) = v0;
        *(float4*)(Wo_s + row * WPITCH + col4 * 4) = v1;
        *(float4*)(Wg_s + row * WPITCH + col4 * 4) = v2;
    }
    int h = t >> 5;
    float qv = d_q[t], bvv = bv[t], bov = bo[t];
    for (int k = 0; k < rpb; k++) {
        int r = blockIdx.x * rpb + k;
        if (r >= R_REG) break;
        __syncthreads();
        for (int idx = t; idx < NHEAD * DIM / 4; idx += blockDim.x)
            ((float4*)u_s)[idx] = ((const float4*)d_u)[(size_t)r * 128 + idx];
        float flag = d_flag[r];
        __syncthreads();
        // stage 1: pooled[j] = Wv[j,:].u_h + flag*bv[j];  O = q + pooled
        {
            const float4* wr = (const float4*)(Wv_s + t * WPITCH);
            const float4* uh = (const float4*)(u_s + h * DIM);
            float acc[4] = {0.f, 0.f, 0.f, 0.f};
            #pragma unroll
            for (int i = 0; i < DIM / 4; i++) {
                float4 w = wr[i]; float4 uu = uh[i];
                float a = acc[i & 3];
                a = fmaf(w.x, uu.x, a); a = fmaf(w.y, uu.y, a);
                a = fmaf(w.z, uu.z, a); a = fmaf(w.w, uu.w, a);
                acc[i & 3] = a;
            }
            O_s[t] = qv + (acc[0] + acc[1]) + (acc[2] + acc[3]) + flag * bvv;
        }
        __syncthreads();
        // stage 2: O2 = O + relu(Wo O + bo)
        {
            const float4* wr = (const float4*)(Wo_s + t * WPITCH);
            const float4* ov = (const float4*)O_s;
            float acc[4] = {bov, 0.f, 0.f, 0.f};
            #pragma unroll
            for (int i = 0; i < DIM / 4; i++) {
                float4 w = wr[i]; float4 o = ov[i];
                float a = acc[i & 3];
                a = fmaf(w.x, o.x, a); a = fmaf(w.y, o.y, a);
                a = fmaf(w.z, o.z, a); a = fmaf(w.w, o.w, a);
                acc[i & 3] = a;
            }
            O2_s[t] = O_s[t] + fmaxf((acc[0] + acc[1]) + (acc[2] + acc[3]), 0.f);
        }
        __syncthreads();
        // stage 3: h = Wg O2  -> global
        {
            const float4* wr = (const float4*)(Wg_s + t * WPITCH);
            const float4* ov = (const float4*)O2_s;
            float acc[4] = {0.f, 0.f, 0.f, 0.f};
            #pragma unroll
            for (int i = 0; i < DIM / 4; i++) {
                float4 w = wr[i]; float4 o = ov[i];
                float a = acc[i & 3];
                a = fmaf(w.x, o.x, a); a = fmaf(w.y, o.y, a);
                a = fmaf(w.z, o.z, a); a = fmaf(w.w, o.w, a);
                acc[i & 3] = a;
            }
            d_hbuf[(size_t)r * DIM + t] = (acc[0] + acc[1]) + (acc[2] + acc[3]);
        }
    }
}

// ---------------- K5: edge scatter out[dst] += norm * h[src] (warp per edge) ----------------
__global__ void k_edge(const int* __restrict__ adj, int E, float* __restrict__ out) {
    int widx = (blockIdx.x * blockDim.x + threadIdx.x) >> 5;
    int lane = threadIdx.x & 31;
    if (widx >= E) return;
    int s = adj[widx], d = adj[E + widx];
    float norm = rsqrtf(fmaxf(d_deg[s], 1e-12f)) * rsqrtf(fmaxf(d_deg[d], 1e-12f));
    const float* hr = d_hbuf + (size_t)s * DIM;
    float* orow = out + (size_t)d * DIM;
    #pragma unroll
    for (int j = lane; j < DIM; j += 32)
        atomicAdd(&orow[j], norm * hr[j]);
}

// ---------------- K6: self loop + PReLU ----------------
__global__ void k_final(const float* __restrict__ prelu, float* __restrict__ out) {
    int idx = blockIdx.x * blockDim.x + threadIdx.x;
    if (idx >= R_REG * DIM) return;
    int r = idx >> 7, j = idx & 127;
    float dis = rsqrtf(fmaxf(d_deg[r], 1e-12f));
    float val = out[idx] + dis * dis * d_hbuf[idx];
    out[idx] = val > 0.f ? val : prelu[j] * val;
}

// ---------------- launch ----------------
extern "C" void kernel_launch(void* const* d_in, const int* in_sizes, int n_in,
                              void* d_out, int out_size) {
    const float* x    = (const float*)d_in[0];
    const int*   zone = (const int*)d_in[1];
    const int*   adj  = (const int*)d_in[2];
    const float* S    = (const float*)d_in[3];
    const float* Wq   = (const float*)d_in[4];
    const float* bq   = (const float*)d_in[5];
    const float* Wk   = (const float*)d_in[6];
    const float* bk   = (const float*)d_in[7];
    const float* Wv   = (const float*)d_in[8];
    const float* bv   = (const float*)d_in[9];
    const float* Wo   = (const float*)d_in[10];
    const float* bo   = (const float*)d_in[11];
    const float* Wg   = (const float*)d_in[12];
    const float* bg   = (const float*)d_in[13];
    const float* prelu = (const float*)d_in[14];
    float* out = (float*)d_out;
    int N = in_sizes[0] / DIM;
    int E = in_sizes[2] / 2;

    // K0: init + histogram + setup
    int nbI = (R_REG * DIM + 255) / 256;
    int nbH = (N + HIST_CHUNK - 1) / HIST_CHUNK;
    k_init_setup<<<nbI + nbH + 1, 256>>>(bg, out, S, Wq, bq, Wk, bk, zone, N, nbI, nbH);

    // K1: scan (also resets d_hist for next graph replay)
    k_scan<<<1, 256>>>();

    // K2: counting-sort scatter (4 pts/thread) + deg blocks
    int nbS = (N + 1023) / 1024;
    int nbD = (E + 255) / 256;
    k_sort<<<nbS + nbD, 256>>>(zone, adj, N, E, nbS);

    // K3: fused score+accumulate — single pass over x, ILP-4 + order prefetch
    k_accum<<<R_REG, 128>>>(x);

    int smem_epi = (3 * DIM * WPITCH + NHEAD * DIM + 2 * DIM) * (int)sizeof(float);
    cudaFuncSetAttribute(k_epilogue, cudaFuncAttributeMaxDynamicSharedMemorySize, smem_epi);
    int rpb = 14;
    k_epilogue<<<(R_REG + rpb - 1) / rpb, 128, smem_epi>>>(Wv, bv, Wo, bo, Wg, rpb);

    k_edge<<<(E * 32 + 255) / 256, 256>>>(adj, E, out);
    k_final<<<(R_REG * DIM + 255) / 256, 256>>>(prelu, out);
}

// round 10
// speedup vs baseline: 1.4159x; 1.1097x over previous
#include <cuda_runtime.h>
#include <math.h>

#define R_REG 2000
#define NHEAD 4
#define DIM   128
#define DH    32
#define NMAX  500000
#define WPITCH 132   // smem pitch (floats) for conflict-free float4 matvec reads
#define HIST_CHUNK 16384

// ---------------- scratch (device globals; no allocation allowed) ----------------
__device__ float d_q[DIM];                      // PMA seed query (flattened)
__device__ float d_A[NHEAD * DIM];              // folded score matrix (incl 1/sqrt(D))
__device__ float d_c[NHEAD];                    // folded score bias
__device__ int   d_hist[R_REG];                 // zeroed by fused scan after reading (replay-safe)
__device__ int   d_starts[R_REG + 1];
__device__ int   d_cursor[R_REG];
__device__ int   d_order[NMAX + 16];            // +16 pad so prefetch needs no bounds checks
__device__ int   d_tick;                        // last-block ticket for fused scan
__device__ __align__(16) float d_u[R_REG * NHEAD * DIM];  // normalized weighted sums of x
__device__ float d_flag[R_REG];                 // 1 if region nonempty
__device__ float d_hbuf[R_REG * DIM];           // GCN h = O @ Wg^T
__device__ float d_deg[R_REG];

// ---------------- K0: init + privatized histogram + fused exclusive scan + setup ----------------
__global__ void k_init_setup(const float* __restrict__ bg, float* __restrict__ out,
                             const float* __restrict__ S, const float* __restrict__ Wq,
                             const float* __restrict__ bq, const float* __restrict__ Wk,
                             const float* __restrict__ bk, const int* __restrict__ zone,
                             int N, int nbI, int nbH) {
    int t = threadIdx.x;
    int b = blockIdx.x;
    if (b < nbI) {
        int i = b * blockDim.x + t;
        if (i < R_REG * DIM) out[i] = bg[i & (DIM - 1)];
        if (i < R_REG) d_deg[i] = 1.0f;   // deg starts at 1 (self loop)
        if (b == 0 && t < 16) d_order[N + t] = 0;  // prefetch pad (valid index 0)
    } else if (b < nbI + nbH) {
        // privatized histogram: one smem pass per chunk, then sparse global flush
        __shared__ int hs[R_REG];
        __shared__ int isLast;
        for (int i = t; i < R_REG; i += 256) hs[i] = 0;
        __syncthreads();
        int base = (b - nbI) * HIST_CHUNK;
        int lim = min(HIST_CHUNK, N - base);
        for (int i = t; i < lim; i += 256) atomicAdd(&hs[zone[base + i]], 1);
        __syncthreads();
        for (int i = t; i < R_REG; i += 256) {
            int v = hs[i];
            if (v) atomicAdd(&d_hist[i], v);
        }
        // ---- last hist block performs the exclusive scan inline (saves a launch) ----
        if (t == 0) {
            __threadfence();
            isLast = (atomicAdd(&d_tick, 1) == nbH - 1) ? 1 : 0;
        }
        __syncthreads();
        if (isLast) {
            if (t == 0) { d_tick = 0; __threadfence(); }
            __shared__ int wsum[8];
            int sbase = t * 8;
            int vals[8]; int s = 0;
            #pragma unroll
            for (int i = 0; i < 8; i++) {
                int idx = sbase + i;
                int v = 0;
                if (idx < R_REG) { v = d_hist[idx]; d_hist[idx] = 0; }  // read + reset
                vals[i] = s; s += v;
            }
            int lane = t & 31, w = t >> 5;
            int inc = s;
            #pragma unroll
            for (int off = 1; off < 32; off <<= 1) {
                int o = __shfl_up_sync(0xffffffffu, inc, off);
                if (lane >= off) inc += o;
            }
            if (lane == 31) wsum[w] = inc;
            __syncthreads();
            if (t == 0) {
                int acc = 0;
                for (int i = 0; i < 8; i++) { int v = wsum[i]; wsum[i] = acc; acc += v; }
                d_starts[R_REG] = acc;
            }
            __syncthreads();
            int texcl = inc - s + wsum[w];
            #pragma unroll
            for (int i = 0; i < 8; i++) {
                int idx = sbase + i;
                if (idx < R_REG) {
                    int st = texcl + vals[i];
                    d_starts[idx] = st;
                    d_cursor[idx] = st;
                }
            }
        }
    } else {
        // ---- setup: q = Wq S + bq ; A = (q^T Wk)/sqrt(D) ----
        __shared__ float S_s[DIM];
        __shared__ float q_s[DIM];
        if (t < DIM) S_s[t] = S[t];
        __syncthreads();
        if (t < DIM) {
            float acc = bq[t];
            const float4* wrow = (const float4*)(Wq + t * DIM);
            const float4* s4 = (const float4*)S_s;
            #pragma unroll
            for (int i = 0; i < DIM / 4; i++) {
                float4 w = wrow[i]; float4 s = s4[i];
                acc = fmaf(w.x, s.x, acc); acc = fmaf(w.y, s.y, acc);
                acc = fmaf(w.z, s.z, acc); acc = fmaf(w.w, s.w, acc);
            }
            q_s[t] = acc;
            d_q[t] = acc;
        }
        __syncthreads();
        if (t < DIM) {
            const float invsq = 0.08838834764831845f;  // 1/sqrt(128)
            for (int h = 0; h < NHEAD; h++) {
                float a = 0.f;
                #pragma unroll 8
                for (int dh = 0; dh < DH; dh++)
                    a = fmaf(q_s[h * DH + dh], Wk[(h * DH + dh) * DIM + t], a);
                d_A[h * DIM + t] = a * invsq;
            }
            if (t < NHEAD) {
                float cc = 0.f;
                for (int dh = 0; dh < DH; dh++) cc = fmaf(q_s[t * DH + dh], bk[t * DH + dh], cc);
                d_c[t] = cc * invsq;
            }
        }
    }
}

// ---------------- K1: counting-sort scatter (4 pts/thread, int4 zone loads) + fused deg ----------------
__global__ void __launch_bounds__(256) k_sort(const int* __restrict__ zone,
                                              const int* __restrict__ adj,
                                              int N, int E, int nbS) {
    if ((int)blockIdx.x >= nbS) {
        int e = (blockIdx.x - nbS) * blockDim.x + threadIdx.x;
        if (e < E) atomicAdd(&d_deg[adj[E + e]], 1.0f);
        return;
    }
    int tid = blockIdx.x * blockDim.x + threadIdx.x;
    int base = tid * 4;
    if (base >= N) return;
    if (base + 3 < N) {
        int4 z = *(const int4*)(zone + base);   // 16B vector load
        // 4 independent atomic chains in flight
        int p0 = atomicAdd(&d_cursor[z.x], 1);
        int p1 = atomicAdd(&d_cursor[z.y], 1);
        int p2 = atomicAdd(&d_cursor[z.z], 1);
        int p3 = atomicAdd(&d_cursor[z.w], 1);
        d_order[p0] = base;
        d_order[p1] = base + 1;
        d_order[p2] = base + 2;
        d_order[p3] = base + 3;
    } else {
        for (int n = base; n < N; n++) {
            int pos = atomicAdd(&d_cursor[zone[n]], 1);
            d_order[pos] = n;
        }
    }
}

// 4-head warp reduction in 9 shfls; ALL lanes of 8-lane group g end with head-g's full sum
__device__ __forceinline__ float headred(float s0, float s1, float s2, float s3, int lane) {
    float o0 = __shfl_xor_sync(0xffffffffu, s0, 16);
    float o1 = __shfl_xor_sync(0xffffffffu, s1, 16);
    float o2 = __shfl_xor_sync(0xffffffffu, s2, 16);
    float o3 = __shfl_xor_sync(0xffffffffu, s3, 16);
    float t0, t1;
    if (lane < 16) { t0 = s0 + o0; t1 = s1 + o1; } else { t0 = s2 + o2; t1 = s3 + o3; }
    float p0 = __shfl_xor_sync(0xffffffffu, t0, 8);
    float p1 = __shfl_xor_sync(0xffffffffu, t1, 8);
    float v = ((lane & 8) == 0) ? (t0 + p0) : (t1 + p1);
    v += __shfl_xor_sync(0xffffffffu, v, 4);
    v += __shfl_xor_sync(0xffffffffu, v, 2);
    v += __shfl_xor_sync(0xffffffffu, v, 1);
    return v;
}

// ---------------- K2: single-pass score + weighted accumulation (x read ONCE) ----------------
// Steady-state loop has NO bounds checks or tail masking (main/tail split; d_order padded).
__global__ void __launch_bounds__(128) k_accum(const float* __restrict__ x) {
    int r = blockIdx.x;
    int t = threadIdx.x;
    int w = t >> 5, lane = t & 31;
    int start = d_starts[r], end = d_starts[r + 1];
    const float4* x4 = (const float4*)x;
    const float4* A4 = (const float4*)d_A;
    float4 A0 = A4[0 * 32 + lane], A1 = A4[1 * 32 + lane];
    float4 A2 = A4[2 * 32 + lane], A3 = A4[3 * 32 + lane];
    float cb = d_c[lane >> 3];   // head bias (head = lane>>3); v holds that head's sum
    float4 a0 = make_float4(0.f,0.f,0.f,0.f), a1 = a0, a2 = a0, a3 = a0;
    float dn0 = 0.f, dn1 = 0.f, dn2 = 0.f, dn3 = 0.f;
    #define DOT4(a, v) ((a).x*(v).x + (a).y*(v).y + (a).z*(v).z + (a).w*(v).w)
    int p = start + 4 * w;
    // unconditional preload (d_order padded by 16 zeroed entries)
    int n0 = __ldg(&d_order[p]);
    int n1 = __ldg(&d_order[p + 1]);
    int n2 = __ldg(&d_order[p + 2]);
    int n3 = __ldg(&d_order[p + 3]);
    #pragma unroll 1
    while (p + 4 <= end) {
        // 4 independent x-row gathers (2KB in flight per warp)
        float4 xv0 = __ldg(&x4[(size_t)n0 * 32 + lane]);
        float4 xv1 = __ldg(&x4[(size_t)n1 * 32 + lane]);
        float4 xv2 = __ldg(&x4[(size_t)n2 * 32 + lane]);
        float4 xv3 = __ldg(&x4[(size_t)n3 * 32 + lane]);
        // unguarded prefetch of next quad (pad-safe)
        int pn = p + 16;
        n0 = __ldg(&d_order[pn]);
        n1 = __ldg(&d_order[pn + 1]);
        n2 = __ldg(&d_order[pn + 2]);
        n3 = __ldg(&d_order[pn + 3]);
        // 4 interleaved score reductions (shfl latencies hide each other)
        float v0 = headred(DOT4(A0,xv0), DOT4(A1,xv0), DOT4(A2,xv0), DOT4(A3,xv0), lane);
        float v1 = headred(DOT4(A0,xv1), DOT4(A1,xv1), DOT4(A2,xv1), DOT4(A3,xv1), lane);
        float v2 = headred(DOT4(A0,xv2), DOT4(A1,xv2), DOT4(A2,xv2), DOT4(A3,xv2), lane);
        float v3 = headred(DOT4(A0,xv3), DOT4(A1,xv3), DOT4(A2,xv3), DOT4(A3,xv3), lane);
        float ev0 = __expf(v0 + cb);
        float ev1 = __expf(v1 + cb);
        float ev2 = __expf(v2 + cb);
        float ev3 = __expf(v3 + cb);
        float e00 = __shfl_sync(0xffffffffu, ev0, 0);
        float e01 = __shfl_sync(0xffffffffu, ev0, 8);
        float e02 = __shfl_sync(0xffffffffu, ev0, 16);
        float e03 = __shfl_sync(0xffffffffu, ev0, 24);
        float e10 = __shfl_sync(0xffffffffu, ev1, 0);
        float e11 = __shfl_sync(0xffffffffu, ev1, 8);
        float e12 = __shfl_sync(0xffffffffu, ev1, 16);
        float e13 = __shfl_sync(0xffffffffu, ev1, 24);
        float e20 = __shfl_sync(0xffffffffu, ev2, 0);
        float e21 = __shfl_sync(0xffffffffu, ev2, 8);
        float e22 = __shfl_sync(0xffffffffu, ev2, 16);
        float e23 = __shfl_sync(0xffffffffu, ev2, 24);
        float e30 = __shfl_sync(0xffffffffu, ev3, 0);
        float e31 = __shfl_sync(0xffffffffu, ev3, 8);
        float e32 = __shfl_sync(0xffffffffu, ev3, 16);
        float e33 = __shfl_sync(0xffffffffu, ev3, 24);
        a0.x = fmaf(e00, xv0.x, a0.x); a0.y = fmaf(e00, xv0.y, a0.y);
        a0.z = fmaf(e00, xv0.z, a0.z); a0.w = fmaf(e00, xv0.w, a0.w);
        a1.x = fmaf(e01, xv0.x, a1.x); a1.y = fmaf(e01, xv0.y, a1.y);
        a1.z = fmaf(e01, xv0.z, a1.z); a1.w = fmaf(e01, xv0.w, a1.w);
        a2.x = fmaf(e02, xv0.x, a2.x); a2.y = fmaf(e02, xv0.y, a2.y);
        a2.z = fmaf(e02, xv0.z, a2.z); a2.w = fmaf(e02, xv0.w, a2.w);
        a3.x = fmaf(e03, xv0.x, a3.x); a3.y = fmaf(e03, xv0.y, a3.y);
        a3.z = fmaf(e03, xv0.z, a3.z); a3.w = fmaf(e03, xv0.w, a3.w);
        dn0 += e00; dn1 += e01; dn2 += e02; dn3 += e03;
        a0.x = fmaf(e10, xv1.x, a0.x); a0.y = fmaf(e10, xv1.y, a0.y);
        a0.z = fmaf(e10, xv1.z, a0.z); a0.w = fmaf(e10, xv1.w, a0.w);
        a1.x = fmaf(e11, xv1.x, a1.x); a1.y = fmaf(e11, xv1.y, a1.y);
        a1.z = fmaf(e11, xv1.z, a1.z); a1.w = fmaf(e11, xv1.w, a1.w);
        a2.x = fmaf(e12, xv1.x, a2.x); a2.y = fmaf(e12, xv1.y, a2.y);
        a2.z = fmaf(e12, xv1.z, a2.z); a2.w = fmaf(e12, xv1.w, a2.w);
        a3.x = fmaf(e13, xv1.x, a3.x); a3.y = fmaf(e13, xv1.y, a3.y);
        a3.z = fmaf(e13, xv1.z, a3.z); a3.w = fmaf(e13, xv1.w, a3.w);
        dn0 += e10; dn1 += e11; dn2 += e12; dn3 += e13;
        a0.x = fmaf(e20, xv2.x, a0.x); a0.y = fmaf(e20, xv2.y, a0.y);
        a0.z = fmaf(e20, xv2.z, a0.z); a0.w = fmaf(e20, xv2.w, a0.w);
        a1.x = fmaf(e21, xv2.x, a1.x); a1.y = fmaf(e21, xv2.y, a1.y);
        a1.z = fmaf(e21, xv2.z, a1.z); a1.w = fmaf(e21, xv2.w, a1.w);
        a2.x = fmaf(e22, xv2.x, a2.x); a2.y = fmaf(e22, xv2.y, a2.y);
        a2.z = fmaf(e22, xv2.z, a2.z); a2.w = fmaf(e22, xv2.w, a2.w);
        a3.x = fmaf(e23, xv2.x, a3.x); a3.y = fmaf(e23, xv2.y, a3.y);
        a3.z = fmaf(e23, xv2.z, a3.z); a3.w = fmaf(e23, xv2.w, a3.w);
        dn0 += e20; dn1 += e21; dn2 += e22; dn3 += e23;
        a0.x = fmaf(e30, xv3.x, a0.x); a0.y = fmaf(e30, xv3.y, a0.y);
        a0.z = fmaf(e30, xv3.z, a0.z); a0.w = fmaf(e30, xv3.w, a0.w);
        a1.x = fmaf(e31, xv3.x, a1.x); a1.y = fmaf(e31, xv3.y, a1.y);
        a1.z = fmaf(e31, xv3.z, a1.z); a1.w = fmaf(e31, xv3.w, a1.w);
        a2.x = fmaf(e32, xv3.x, a2.x); a2.y = fmaf(e32, xv3.y, a2.y);
        a2.z = fmaf(e32, xv3.z, a2.z); a2.w = fmaf(e32, xv3.w, a2.w);
        a3.x = fmaf(e33, xv3.x, a3.x); a3.y = fmaf(e33, xv3.y, a3.y);
        a3.z = fmaf(e33, xv3.z, a3.z); a3.w = fmaf(e33, xv3.w, a3.w);
        dn0 += e30; dn1 += e31; dn2 += e32; dn3 += e33;
        p = pn;
    }
    // tail: up to 3 leftover points for this warp
    for (int q = p; q < end && q < p + 4; q++) {
        int n = __ldg(&d_order[q]);
        float4 xv = __ldg(&x4[(size_t)n * 32 + lane]);
        float v = headred(DOT4(A0,xv), DOT4(A1,xv), DOT4(A2,xv), DOT4(A3,xv), lane);
        float ev = __expf(v + cb);
        float e0 = __shfl_sync(0xffffffffu, ev, 0);
        float e1 = __shfl_sync(0xffffffffu, ev, 8);
        float e2 = __shfl_sync(0xffffffffu, ev, 16);
        float e3 = __shfl_sync(0xffffffffu, ev, 24);
        a0.x = fmaf(e0, xv.x, a0.x); a0.y = fmaf(e0, xv.y, a0.y);
        a0.z = fmaf(e0, xv.z, a0.z); a0.w = fmaf(e0, xv.w, a0.w);
        a1.x = fmaf(e1, xv.x, a1.x); a1.y = fmaf(e1, xv.y, a1.y);
        a1.z = fmaf(e1, xv.z, a1.z); a1.w = fmaf(e1, xv.w, a1.w);
        a2.x = fmaf(e2, xv.x, a2.x); a2.y = fmaf(e2, xv.y, a2.y);
        a2.z = fmaf(e2, xv.z, a2.z); a2.w = fmaf(e2, xv.w, a2.w);
        a3.x = fmaf(e3, xv.x, a3.x); a3.y = fmaf(e3, xv.y, a3.y);
        a3.z = fmaf(e3, xv.z, a3.z); a3.w = fmaf(e3, xv.w, a3.w);
        dn0 += e0; dn1 += e1; dn2 += e2; dn3 += e3;
    }
    #undef DOT4
    // cross-warp combine in smem: part[warp][head][lane] (float4 = dims 4*lane..4*lane+3)
    __shared__ float4 part[4][4][32];
    __shared__ float pdn[4][4];
    part[w][0][lane] = a0; part[w][1][lane] = a1;
    part[w][2][lane] = a2; part[w][3][lane] = a3;
    if (lane == 0) { pdn[w][0] = dn0; pdn[w][1] = dn1; pdn[w][2] = dn2; pdn[w][3] = dn3; }
    __syncthreads();
    // thread t = (h=w, lane) finalizes head w
    int h = w;
    float4 s0 = part[0][h][lane], s1 = part[1][h][lane];
    float4 s2 = part[2][h][lane], s3 = part[3][h][lane];
    float4 u;
    u.x = s0.x + s1.x + s2.x + s3.x;
    u.y = s0.y + s1.y + s2.y + s3.y;
    u.z = s0.z + s1.z + s2.z + s3.z;
    u.w = s0.w + s1.w + s2.w + s3.w;
    float dn = pdn[0][h] + pdn[1][h] + pdn[2][h] + pdn[3][h];
    float inv = dn > 0.f ? 1.0f / dn : 0.f;
    u.x *= inv; u.y *= inv; u.z *= inv; u.w *= inv;
    ((float4*)d_u)[(size_t)r * 128 + h * 32 + lane] = u;
    if (t == 0) d_flag[r] = (end > start) ? 1.0f : 0.0f;
}

// ---------------- K3: fused epilogue, 2 regions per 256-thread block ----------------
__global__ void __launch_bounds__(256) k_epilogue(
        const float* __restrict__ Wv, const float* __restrict__ bv,
        const float* __restrict__ Wo, const float* __restrict__ bo,
        const float* __restrict__ Wg, int rpb) {
    extern __shared__ float sm[];
    float* Wv_s = sm;
    float* Wo_s = Wv_s + DIM * WPITCH;
    float* Wg_s = Wo_s + DIM * WPITCH;
    float* u_s  = Wg_s + DIM * WPITCH;   // 2 * 512
    float* O_s  = u_s + 2 * NHEAD * DIM; // 2 * 128
    float* O2_s = O_s + 2 * DIM;         // 2 * 128
    int t = threadIdx.x;
    int sub = t >> 7;      // which of the 2 concurrent regions
    int tt = t & 127;      // thread index within region
    for (int idx = t; idx < DIM * DIM / 4; idx += 256) {
        int row = idx >> 5, col4 = idx & 31;
        float4 v0 = ((const float4*)Wv)[idx];
        float4 v1 = ((const float4*)Wo)[idx];
        float4 v2 = ((const float4*)Wg)[idx];
        *(float4*)(Wv_s + row * WPITCH + col4 * 4) = v0;
        *(float4*)(Wo_s + row * WPITCH + col4 * 4) = v1;
        *(float4*)(Wg_s + row * WPITCH + col4 * 4) = v2;
    }
    int h = tt >> 5;
    float qv = d_q[tt], bvv = bv[tt], bov = bo[tt];
    float* mu  = u_s  + sub * (NHEAD * DIM);
    float* mO  = O_s  + sub * DIM;
    float* mO2 = O2_s + sub * DIM;
    int npair = rpb >> 1;
    for (int k = 0; k < npair; k++) {
        int r = blockIdx.x * rpb + 2 * k + sub;
        bool active = (r < R_REG);
        int rc = active ? r : (R_REG - 1);
        __syncthreads();
        ((float4*)mu)[tt] = ((const float4*)d_u)[(size_t)rc * 128 + tt];
        float flag = d_flag[rc];
        __syncthreads();
        // stage 1: pooled[j] = Wv[j,:].u_h + flag*bv[j];  O = q + pooled
        {
            const float4* wr = (const float4*)(Wv_s + tt * WPITCH);
            const float4* uh = (const float4*)(mu + h * DIM);
            float acc[4] = {0.f, 0.f, 0.f, 0.f};
            #pragma unroll
            for (int i = 0; i < DIM / 4; i++) {
                float4 w = wr[i]; float4 uu = uh[i];
                float a = acc[i & 3];
                a = fmaf(w.x, uu.x, a); a = fmaf(w.y, uu.y, a);
                a = fmaf(w.z, uu.z, a); a = fmaf(w.w, uu.w, a);
                acc[i & 3] = a;
            }
            mO[tt] = qv + (acc[0] + acc[1]) + (acc[2] + acc[3]) + flag * bvv;
        }
        __syncthreads();
        // stage 2: O2 = O + relu(Wo O + bo)
        {
            const float4* wr = (const float4*)(Wo_s + tt * WPITCH);
            const float4* ov = (const float4*)mO;
            float acc[4] = {bov, 0.f, 0.f, 0.f};
            #pragma unroll
            for (int i = 0; i < DIM / 4; i++) {
                float4 w = wr[i]; float4 o = ov[i];
                float a = acc[i & 3];
                a = fmaf(w.x, o.x, a); a = fmaf(w.y, o.y, a);
                a = fmaf(w.z, o.z, a); a = fmaf(w.w, o.w, a);
                acc[i & 3] = a;
            }
            mO2[tt] = mO[tt] + fmaxf((acc[0] + acc[1]) + (acc[2] + acc[3]), 0.f);
        }
        __syncthreads();
        // stage 3: h = Wg O2  -> global
        {
            const float4* wr = (const float4*)(Wg_s + tt * WPITCH);
            const float4* ov = (const float4*)mO2;
            float acc[4] = {0.f, 0.f, 0.f, 0.f};
            #pragma unroll
            for (int i = 0; i < DIM / 4; i++) {
                float4 w = wr[i]; float4 o = ov[i];
                float a = acc[i & 3];
                a = fmaf(w.x, o.x, a); a = fmaf(w.y, o.y, a);
                a = fmaf(w.z, o.z, a); a = fmaf(w.w, o.w, a);
                acc[i & 3] = a;
            }
            if (active)
                d_hbuf[(size_t)r * DIM + tt] = (acc[0] + acc[1]) + (acc[2] + acc[3]);
        }
    }
}

// ---------------- K4: edge scatter out[dst] += norm * h[src] (warp per edge) ----------------
__global__ void k_edge(const int* __restrict__ adj, int E, float* __restrict__ out) {
    int widx = (blockIdx.x * blockDim.x + threadIdx.x) >> 5;
    int lane = threadIdx.x & 31;
    if (widx >= E) return;
    int s = adj[widx], d = adj[E + widx];
    float norm = rsqrtf(fmaxf(d_deg[s], 1e-12f)) * rsqrtf(fmaxf(d_deg[d], 1e-12f));
    const float* hr = d_hbuf + (size_t)s * DIM;
    float* orow = out + (size_t)d * DIM;
    #pragma unroll
    for (int j = lane; j < DIM; j += 32)
        atomicAdd(&orow[j], norm * hr[j]);
}

// ---------------- K5: self loop + PReLU ----------------
__global__ void k_final(const float* __restrict__ prelu, float* __restrict__ out) {
    int idx = blockIdx.x * blockDim.x + threadIdx.x;
    if (idx >= R_REG * DIM) return;
    int r = idx >> 7, j = idx & 127;
    float dis = rsqrtf(fmaxf(d_deg[r], 1e-12f));
    float val = out[idx] + dis * dis * d_hbuf[idx];
    out[idx] = val > 0.f ? val : prelu[j] * val;
}

// ---------------- launch ----------------
extern "C" void kernel_launch(void* const* d_in, const int* in_sizes, int n_in,
                              void* d_out, int out_size) {
    const float* x    = (const float*)d_in[0];
    const int*   zone = (const int*)d_in[1];
    const int*   adj  = (const int*)d_in[2];
    const float* S    = (const float*)d_in[3];
    const float* Wq   = (const float*)d_in[4];
    const float* bq   = (const float*)d_in[5];
    const float* Wk   = (const float*)d_in[6];
    const float* bk   = (const float*)d_in[7];
    const float* Wv   = (const float*)d_in[8];
    const float* bv   = (const float*)d_in[9];
    const float* Wo   = (const float*)d_in[10];
    const float* bo   = (const float*)d_in[11];
    const float* Wg   = (const float*)d_in[12];
    const float* bg   = (const float*)d_in[13];
    const float* prelu = (const float*)d_in[14];
    float* out = (float*)d_out;
    int N = in_sizes[0] / DIM;
    int E = in_sizes[2] / 2;

    // K0: init + histogram + fused scan + setup
    int nbI = (R_REG * DIM + 255) / 256;
    int nbH = (N + HIST_CHUNK - 1) / HIST_CHUNK;
    k_init_setup<<<nbI + nbH + 1, 256>>>(bg, out, S, Wq, bq, Wk, bk, zone, N, nbI, nbH);

    // K1: counting-sort scatter (4 pts/thread) + deg blocks
    int nbS = (N + 1023) / 1024;
    int nbD = (E + 255) / 256;
    k_sort<<<nbS + nbD, 256>>>(zone, adj, N, E, nbS);

    // K2: fused score+accumulate — single pass over x, ILP-4, clean steady-state loop
    k_accum<<<R_REG, 128>>>(x);

    // K3: epilogue — 2 regions per 256-thread block
    int smem_epi = (3 * DIM * WPITCH + 2 * (NHEAD * DIM + 2 * DIM)) * (int)sizeof(float);
    cudaFuncSetAttribute(k_epilogue, cudaFuncAttributeMaxDynamicSharedMemorySize, smem_epi);
    int rpb = 14;
    k_epilogue<<<(R_REG + rpb - 1) / rpb, 256, smem_epi>>>(Wv, bv, Wo, bo, Wg, rpb);

    k_edge<<<(E * 32 + 255) / 256, 256>>>(adj, E, out);
    k_final<<<(R_REG * DIM + 255) / 256, 256>>>(prelu, out);
}

// round 12
// speedup vs baseline: 1.4469x; 1.0219x over previous
#include <cuda_runtime.h>
#include <math.h>

#define R_REG 2000
#define NHEAD 4
#define DIM   128
#define DH    32
#define NMAX  500000
#define WPITCH 132   // smem pitch (floats) for conflict-free float4 matvec reads
#define HIST_CHUNK 16384
#define EPI_SUBS 4   // concurrent regions per epilogue block

// ---------------- scratch (device globals; no allocation allowed) ----------------
__device__ float d_q[DIM];                      // PMA seed query (flattened)
__device__ float d_A[NHEAD * DIM];              // folded score matrix (incl 1/sqrt(D))
__device__ float d_c[NHEAD];                    // folded score bias
__device__ int   d_hist[R_REG];                 // zeroed by fused scan after reading (replay-safe)
__device__ int   d_starts[R_REG + 1];
__device__ int   d_cursor[R_REG];
__device__ int   d_order[NMAX + 16];            // +16 pad so prefetch needs no bounds checks
__device__ int   d_tick;                        // last-block ticket for fused scan
__device__ __align__(16) float d_u[R_REG * NHEAD * DIM];  // normalized weighted sums of x
__device__ float d_flag[R_REG];                 // 1 if region nonempty
__device__ float d_hbuf[R_REG * DIM];           // GCN h = O @ Wg^T
__device__ float d_deg[R_REG];

// ---------------- K0: init + privatized histogram + fused exclusive scan + setup ----------------
__global__ void k_init_setup(const float* __restrict__ bg, float* __restrict__ out,
                             const float* __restrict__ S, const float* __restrict__ Wq,
                             const float* __restrict__ bq, const float* __restrict__ Wk,
                             const float* __restrict__ bk, const int* __restrict__ zone,
                             int N, int nbI, int nbH) {
    int t = threadIdx.x;
    int b = blockIdx.x;
    if (b < nbI) {
        int i = b * blockDim.x + t;
        if (i < R_REG * DIM) out[i] = bg[i & (DIM - 1)];
        if (i < R_REG) d_deg[i] = 1.0f;   // deg starts at 1 (self loop)
        if (b == 0 && t < 16) d_order[N + t] = 0;  // prefetch pad (valid index 0)
    } else if (b < nbI + nbH) {
        // privatized histogram: one smem pass per chunk, then sparse global flush
        __shared__ int hs[R_REG];
        __shared__ int isLast;
        for (int i = t; i < R_REG; i += 256) hs[i] = 0;
        __syncthreads();
        int base = (b - nbI) * HIST_CHUNK;
        int lim = min(HIST_CHUNK, N - base);
        for (int i = t; i < lim; i += 256) atomicAdd(&hs[zone[base + i]], 1);
        __syncthreads();
        for (int i = t; i < R_REG; i += 256) {
            int v = hs[i];
            if (v) atomicAdd(&d_hist[i], v);
        }
        // ---- last hist block performs the exclusive scan inline (saves a launch) ----
        if (t == 0) {
            __threadfence();
            isLast = (atomicAdd(&d_tick, 1) == nbH - 1) ? 1 : 0;
        }
        __syncthreads();
        if (isLast) {
            if (t == 0) { d_tick = 0; __threadfence(); }
            __shared__ int wsum[8];
            int sbase = t * 8;
            int vals[8]; int s = 0;
            #pragma unroll
            for (int i = 0; i < 8; i++) {
                int idx = sbase + i;
                int v = 0;
                if (idx < R_REG) { v = d_hist[idx]; d_hist[idx] = 0; }  // read + reset
                vals[i] = s; s += v;
            }
            int lane = t & 31, w = t >> 5;
            int inc = s;
            #pragma unroll
            for (int off = 1; off < 32; off <<= 1) {
                int o = __shfl_up_sync(0xffffffffu, inc, off);
                if (lane >= off) inc += o;
            }
            if (lane == 31) wsum[w] = inc;
            __syncthreads();
            if (t == 0) {
                int acc = 0;
                for (int i = 0; i < 8; i++) { int v = wsum[i]; wsum[i] = acc; acc += v; }
                d_starts[R_REG] = acc;
            }
            __syncthreads();
            int texcl = inc - s + wsum[w];
            #pragma unroll
            for (int i = 0; i < 8; i++) {
                int idx = sbase + i;
                if (idx < R_REG) {
                    int st = texcl + vals[i];
                    d_starts[idx] = st;
                    d_cursor[idx] = st;
                }
            }
        }
    } else {
        // ---- setup: q = Wq S + bq ; A = (q^T Wk)/sqrt(D) ----
        __shared__ float S_s[DIM];
        __shared__ float q_s[DIM];
        if (t < DIM) S_s[t] = S[t];
        __syncthreads();
        if (t < DIM) {
            float acc = bq[t];
            const float4* wrow = (const float4*)(Wq + t * DIM);
            const float4* s4 = (const float4*)S_s;
            #pragma unroll
            for (int i = 0; i < DIM / 4; i++) {
                float4 w = wrow[i]; float4 s = s4[i];
                acc = fmaf(w.x, s.x, acc); acc = fmaf(w.y, s.y, acc);
                acc = fmaf(w.z, s.z, acc); acc = fmaf(w.w, s.w, acc);
            }
            q_s[t] = acc;
            d_q[t] = acc;
        }
        __syncthreads();
        if (t < DIM) {
            const float invsq = 0.08838834764831845f;  // 1/sqrt(128)
            for (int h = 0; h < NHEAD; h++) {
                float a = 0.f;
                #pragma unroll 8
                for (int dh = 0; dh < DH; dh++)
                    a = fmaf(q_s[h * DH + dh], Wk[(h * DH + dh) * DIM + t], a);
                d_A[h * DIM + t] = a * invsq;
            }
            if (t < NHEAD) {
                float cc = 0.f;
                for (int dh = 0; dh < DH; dh++) cc = fmaf(q_s[t * DH + dh], bk[t * DH + dh], cc);
                d_c[t] = cc * invsq;
            }
        }
    }
}

// ---------------- K1: counting-sort scatter (4 pts/thread, int4 zone loads) + fused deg ----------------
__global__ void __launch_bounds__(256) k_sort(const int* __restrict__ zone,
                                              const int* __restrict__ adj,
                                              int N, int E, int nbS) {
    if ((int)blockIdx.x >= nbS) {
        int e = (blockIdx.x - nbS) * blockDim.x + threadIdx.x;
        if (e < E) atomicAdd(&d_deg[adj[E + e]], 1.0f);
        return;
    }
    int tid = blockIdx.x * blockDim.x + threadIdx.x;
    int base = tid * 4;
    if (base >= N) return;
    if (base + 3 < N) {
        int4 z = *(const int4*)(zone + base);   // 16B vector load
        // 4 independent atomic chains in flight
        int p0 = atomicAdd(&d_cursor[z.x], 1);
        int p1 = atomicAdd(&d_cursor[z.y], 1);
        int p2 = atomicAdd(&d_cursor[z.z], 1);
        int p3 = atomicAdd(&d_cursor[z.w], 1);
        d_order[p0] = base;
        d_order[p1] = base + 1;
        d_order[p2] = base + 2;
        d_order[p3] = base + 3;
    } else {
        for (int n = base; n < N; n++) {
            int pos = atomicAdd(&d_cursor[zone[n]], 1);
            d_order[pos] = n;
        }
    }
}

// 4-head warp reduction in 9 shfls; ALL lanes of 8-lane group g end with head-g's full sum
__device__ __forceinline__ float headred(float s0, float s1, float s2, float s3, int lane) {
    float o0 = __shfl_xor_sync(0xffffffffu, s0, 16);
    float o1 = __shfl_xor_sync(0xffffffffu, s1, 16);
    float o2 = __shfl_xor_sync(0xffffffffu, s2, 16);
    float o3 = __shfl_xor_sync(0xffffffffu, s3, 16);
    float t0, t1;
    if (lane < 16) { t0 = s0 + o0; t1 = s1 + o1; } else { t0 = s2 + o2; t1 = s3 + o3; }
    float p0 = __shfl_xor_sync(0xffffffffu, t0, 8);
    float p1 = __shfl_xor_sync(0xffffffffu, t1, 8);
    float v = ((lane & 8) == 0) ? (t0 + p0) : (t1 + p1);
    v += __shfl_xor_sync(0xffffffffu, v, 4);
    v += __shfl_xor_sync(0xffffffffu, v, 2);
    v += __shfl_xor_sync(0xffffffffu, v, 1);
    return v;
}

// ---------------- K2: single-pass score + weighted accumulation (x read ONCE) ----------------
// Steady-state loop has NO bounds checks or tail masking (main/tail split; d_order padded).
__global__ void __launch_bounds__(128) k_accum(const float* __restrict__ x) {
    int r = blockIdx.x;
    int t = threadIdx.x;
    int w = t >> 5, lane = t & 31;
    int start = d_starts[r], end = d_starts[r + 1];
    const float4* x4 = (const float4*)x;
    const float4* A4 = (const float4*)d_A;
    float4 A0 = A4[0 * 32 + lane], A1 = A4[1 * 32 + lane];
    float4 A2 = A4[2 * 32 + lane], A3 = A4[3 * 32 + lane];
    float cb = d_c[lane >> 3];   // head bias (head = lane>>3); v holds that head's sum
    float4 a0 = make_float4(0.f,0.f,0.f,0.f), a1 = a0, a2 = a0, a3 = a0;
    float dn0 = 0.f, dn1 = 0.f, dn2 = 0.f, dn3 = 0.f;
    #define DOT4(a, v) ((a).x*(v).x + (a).y*(v).y + (a).z*(v).z + (a).w*(v).w)
    int p = start + 4 * w;
    // unconditional preload (d_order padded by 16 zeroed entries)
    int n0 = __ldg(&d_order[p]);
    int n1 = __ldg(&d_order[p + 1]);
    int n2 = __ldg(&d_order[p + 2]);
    int n3 = __ldg(&d_order[p + 3]);
    #pragma unroll 1
    while (p + 4 <= end) {
        // 4 independent x-row gathers (2KB in flight per warp)
        float4 xv0 = __ldg(&x4[(size_t)n0 * 32 + lane]);
        float4 xv1 = __ldg(&x4[(size_t)n1 * 32 + lane]);
        float4 xv2 = __ldg(&x4[(size_t)n2 * 32 + lane]);
        float4 xv3 = __ldg(&x4[(size_t)n3 * 32 + lane]);
        // unguarded prefetch of next quad (pad-safe)
        int pn = p + 16;
        n0 = __ldg(&d_order[pn]);
        n1 = __ldg(&d_order[pn + 1]);
        n2 = __ldg(&d_order[pn + 2]);
        n3 = __ldg(&d_order[pn + 3]);
        // 4 interleaved score reductions (shfl latencies hide each other)
        float v0 = headred(DOT4(A0,xv0), DOT4(A1,xv0), DOT4(A2,xv0), DOT4(A3,xv0), lane);
        float v1 = headred(DOT4(A0,xv1), DOT4(A1,xv1), DOT4(A2,xv1), DOT4(A3,xv1), lane);
        float v2 = headred(DOT4(A0,xv2), DOT4(A1,xv2), DOT4(A2,xv2), DOT4(A3,xv2), lane);
        float v3 = headred(DOT4(A0,xv3), DOT4(A1,xv3), DOT4(A2,xv3), DOT4(A3,xv3), lane);
        float ev0 = __expf(v0 + cb);
        float ev1 = __expf(v1 + cb);
        float ev2 = __expf(v2 + cb);
        float ev3 = __expf(v3 + cb);
        float e00 = __shfl_sync(0xffffffffu, ev0, 0);
        float e01 = __shfl_sync(0xffffffffu, ev0, 8);
        float e02 = __shfl_sync(0xffffffffu, ev0, 16);
        float e03 = __shfl_sync(0xffffffffu, ev0, 24);
        float e10 = __shfl_sync(0xffffffffu, ev1, 0);
        float e11 = __shfl_sync(0xffffffffu, ev1, 8);
        float e12 = __shfl_sync(0xffffffffu, ev1, 16);
        float e13 = __shfl_sync(0xffffffffu, ev1, 24);
        float e20 = __shfl_sync(0xffffffffu, ev2, 0);
        float e21 = __shfl_sync(0xffffffffu, ev2, 8);
        float e22 = __shfl_sync(0xffffffffu, ev2, 16);
        float e23 = __shfl_sync(0xffffffffu, ev2, 24);
        float e30 = __shfl_sync(0xffffffffu, ev3, 0);
        float e31 = __shfl_sync(0xffffffffu, ev3, 8);
        float e32 = __shfl_sync(0xffffffffu, ev3, 16);
        float e33 = __shfl_sync(0xffffffffu, ev3, 24);
        a0.x = fmaf(e00, xv0.x, a0.x); a0.y = fmaf(e00, xv0.y, a0.y);
        a0.z = fmaf(e00, xv0.z, a0.z); a0.w = fmaf(e00, xv0.w, a0.w);
        a1.x = fmaf(e01, xv0.x, a1.x); a1.y = fmaf(e01, xv0.y, a1.y);
        a1.z = fmaf(e01, xv0.z, a1.z); a1.w = fmaf(e01, xv0.w, a1.w);
        a2.x = fmaf(e02, xv0.x, a2.x); a2.y = fmaf(e02, xv0.y, a2.y);
        a2.z = fmaf(e02, xv0.z, a2.z); a2.w = fmaf(e02, xv0.w, a2.w);
        a3.x = fmaf(e03, xv0.x, a3.x); a3.y = fmaf(e03, xv0.y, a3.y);
        a3.z = fmaf(e03, xv0.z, a3.z); a3.w = fmaf(e03, xv0.w, a3.w);
        dn0 += e00; dn1 += e01; dn2 += e02; dn3 += e03;
        a0.x = fmaf(e10, xv1.x, a0.x); a0.y = fmaf(e10, xv1.y, a0.y);
        a0.z = fmaf(e10, xv1.z, a0.z); a0.w = fmaf(e10, xv1.w, a0.w);
        a1.x = fmaf(e11, xv1.x, a1.x); a1.y = fmaf(e11, xv1.y, a1.y);
        a1.z = fmaf(e11, xv1.z, a1.z); a1.w = fmaf(e11, xv1.w, a1.w);
        a2.x = fmaf(e12, xv1.x, a2.x); a2.y = fmaf(e12, xv1.y, a2.y);
        a2.z = fmaf(e12, xv1.z, a2.z); a2.w = fmaf(e12, xv1.w, a2.w);
        a3.x = fmaf(e13, xv1.x, a3.x); a3.y = fmaf(e13, xv1.y, a3.y);
        a3.z = fmaf(e13, xv1.z, a3.z); a3.w = fmaf(e13, xv1.w, a3.w);
        dn0 += e10; dn1 += e11; dn2 += e12; dn3 += e13;
        a0.x = fmaf(e20, xv2.x, a0.x); a0.y = fmaf(e20, xv2.y, a0.y);
        a0.z = fmaf(e20, xv2.z, a0.z); a0.w = fmaf(e20, xv2.w, a0.w);
        a1.x = fmaf(e21, xv2.x, a1.x); a1.y = fmaf(e21, xv2.y, a1.y);
        a1.z = fmaf(e21, xv2.z, a1.z); a1.w = fmaf(e21, xv2.w, a1.w);
        a2.x = fmaf(e22, xv2.x, a2.x); a2.y = fmaf(e22, xv2.y, a2.y);
        a2.z = fmaf(e22, xv2.z, a2.z); a2.w = fmaf(e22, xv2.w, a2.w);
        a3.x = fmaf(e23, xv2.x, a3.x); a3.y = fmaf(e23, xv2.y, a3.y);
        a3.z = fmaf(e23, xv2.z, a3.z); a3.w = fmaf(e23, xv2.w, a3.w);
        dn0 += e20; dn1 += e21; dn2 += e22; dn3 += e23;
        a0.x = fmaf(e30, xv3.x, a0.x); a0.y = fmaf(e30, xv3.y, a0.y);
        a0.z = fmaf(e30, xv3.z, a0.z); a0.w = fmaf(e30, xv3.w, a0.w);
        a1.x = fmaf(e31, xv3.x, a1.x); a1.y = fmaf(e31, xv3.y, a1.y);
        a1.z = fmaf(e31, xv3.z, a1.z); a1.w = fmaf(e31, xv3.w, a1.w);
        a2.x = fmaf(e32, xv3.x, a2.x); a2.y = fmaf(e32, xv3.y, a2.y);
        a2.z = fmaf(e32, xv3.z, a2.z); a2.w = fmaf(e32, xv3.w, a2.w);
        a3.x = fmaf(e33, xv3.x, a3.x); a3.y = fmaf(e33, xv3.y, a3.y);
        a3.z = fmaf(e33, xv3.z, a3.z); a3.w = fmaf(e33, xv3.w, a3.w);
        dn0 += e30; dn1 += e31; dn2 += e32; dn3 += e33;
        p = pn;
    }
    // tail: up to 3 leftover points for this warp
    for (int q = p; q < end && q < p + 4; q++) {
        int n = __ldg(&d_order[q]);
        float4 xv = __ldg(&x4[(size_t)n * 32 + lane]);
        float v = headred(DOT4(A0,xv), DOT4(A1,xv), DOT4(A2,xv), DOT4(A3,xv), lane);
        float ev = __expf(v + cb);
        float e0 = __shfl_sync(0xffffffffu, ev, 0);
        float e1 = __shfl_sync(0xffffffffu, ev, 8);
        float e2 = __shfl_sync(0xffffffffu, ev, 16);
        float e3 = __shfl_sync(0xffffffffu, ev, 24);
        a0.x = fmaf(e0, xv.x, a0.x); a0.y = fmaf(e0, xv.y, a0.y);
        a0.z = fmaf(e0, xv.z, a0.z); a0.w = fmaf(e0, xv.w, a0.w);
        a1.x = fmaf(e1, xv.x, a1.x); a1.y = fmaf(e1, xv.y, a1.y);
        a1.z = fmaf(e1, xv.z, a1.z); a1.w = fmaf(e1, xv.w, a1.w);
        a2.x = fmaf(e2, xv.x, a2.x); a2.y = fmaf(e2, xv.y, a2.y);
        a2.z = fmaf(e2, xv.z, a2.z); a2.w = fmaf(e2, xv.w, a2.w);
        a3.x = fmaf(e3, xv.x, a3.x); a3.y = fmaf(e3, xv.y, a3.y);
        a3.z = fmaf(e3, xv.z, a3.z); a3.w = fmaf(e3, xv.w, a3.w);
        dn0 += e0; dn1 += e1; dn2 += e2; dn3 += e3;
    }
    #undef DOT4
    // cross-warp combine in smem: part[warp][head][lane] (float4 = dims 4*lane..4*lane+3)
    __shared__ float4 part[4][4][32];
    __shared__ float pdn[4][4];
    part[w][0][lane] = a0; part[w][1][lane] = a1;
    part[w][2][lane] = a2; part[w][3][lane] = a3;
    if (lane == 0) { pdn[w][0] = dn0; pdn[w][1] = dn1; pdn[w][2] = dn2; pdn[w][3] = dn3; }
    __syncthreads();
    // thread t = (h=w, lane) finalizes head w
    int h = w;
    float4 s0 = part[0][h][lane], s1 = part[1][h][lane];
    float4 s2 = part[2][h][lane], s3 = part[3][h][lane];
    float4 u;
    u.x = s0.x + s1.x + s2.x + s3.x;
    u.y = s0.y + s1.y + s2.y + s3.y;
    u.z = s0.z + s1.z + s2.z + s3.z;
    u.w = s0.w + s1.w + s2.w + s3.w;
    float dn = pdn[0][h] + pdn[1][h] + pdn[2][h] + pdn[3][h];
    float inv = dn > 0.f ? 1.0f / dn : 0.f;
    u.x *= inv; u.y *= inv; u.z *= inv; u.w *= inv;
    ((float4*)d_u)[(size_t)r * 128 + h * 32 + lane] = u;
    if (t == 0) d_flag[r] = (end > start) ? 1.0f : 0.0f;
}

// ---------------- K3: fused epilogue, 4 regions per 512-thread block ----------------
__global__ void __launch_bounds__(512) k_epilogue(
        const float* __restrict__ Wv, const float* __restrict__ bv,
        const float* __restrict__ Wo, const float* __restrict__ bo,
        const float* __restrict__ Wg, int rpb) {
    extern __shared__ float sm[];
    float* Wv_s = sm;
    float* Wo_s = Wv_s + DIM * WPITCH;
    float* Wg_s = Wo_s + DIM * WPITCH;
    float* u_s  = Wg_s + DIM * WPITCH;          // EPI_SUBS * 512
    float* O_s  = u_s + EPI_SUBS * NHEAD * DIM; // EPI_SUBS * 128
    float* O2_s = O_s + EPI_SUBS * DIM;         // EPI_SUBS * 128
    int t = threadIdx.x;
    int sub = t >> 7;      // which of the 4 concurrent regions
    int tt = t & 127;      // thread index within region
    for (int idx = t; idx < DIM * DIM / 4; idx += 512) {
        int row = idx >> 5, col4 = idx & 31;
        float4 v0 = ((const float4*)Wv)[idx];
        float4 v1 = ((const float4*)Wo)[idx];
        float4 v2 = ((const float4*)Wg)[idx];
        *(float4*)(Wv_s + row * WPITCH + col4 * 4) = v0;
        *(float4*)(Wo_s + row * WPITCH + col4 * 4) = v1;
        *(float4*)(Wg_s + row * WPITCH + col4 * 4) = v2;
    }
    int h = tt >> 5;
    float qv = d_q[tt], bvv = bv[tt], bov = bo[tt];
    float* mu  = u_s  + sub * (NHEAD * DIM);
    float* mO  = O_s  + sub * DIM;
    float* mO2 = O2_s + sub * DIM;
    int ngroup = rpb / EPI_SUBS;
    for (int k = 0; k < ngroup; k++) {
        int r = blockIdx.x * rpb + EPI_SUBS * k + sub;
        bool active = (r < R_REG);
        int rc = active ? r : (R_REG - 1);
        __syncthreads();
        ((float4*)mu)[tt] = ((const float4*)d_u)[(size_t)rc * 128 + tt];
        float flag = d_flag[rc];
        __syncthreads();
        // stage 1: pooled[j] = Wv[j,:].u_h + flag*bv[j];  O = q + pooled
        {
            const float4* wr = (const float4*)(Wv_s + tt * WPITCH);
            const float4* uh = (const float4*)(mu + h * DIM);
            float acc[4] = {0.f, 0.f, 0.f, 0.f};
            #pragma unroll
            for (int i = 0; i < DIM / 4; i++) {
                float4 w = wr[i]; float4 uu = uh[i];
                float a = acc[i & 3];
                a = fmaf(w.x, uu.x, a); a = fmaf(w.y, uu.y, a);
                a = fmaf(w.z, uu.z, a); a = fmaf(w.w, uu.w, a);
                acc[i & 3] = a;
            }
            mO[tt] = qv + (acc[0] + acc[1]) + (acc[2] + acc[3]) + flag * bvv;
        }
        __syncthreads();
        // stage 2: O2 = O + relu(Wo O + bo)
        {
            const float4* wr = (const float4*)(Wo_s + tt * WPITCH);
            const float4* ov = (const float4*)mO;
            float acc[4] = {bov, 0.f, 0.f, 0.f};
            #pragma unroll
            for (int i = 0; i < DIM / 4; i++) {
                float4 w = wr[i]; float4 o = ov[i];
                float a = acc[i & 3];
                a = fmaf(w.x, o.x, a); a = fmaf(w.y, o.y, a);
                a = fmaf(w.z, o.z, a); a = fmaf(w.w, o.w, a);
                acc[i & 3] = a;
            }
            mO2[tt] = mO[tt] + fmaxf((acc[0] + acc[1]) + (acc[2] + acc[3]), 0.f);
        }
        __syncthreads();
        // stage 3: h = Wg O2  -> global
        {
            const float4* wr = (const float4*)(Wg_s + tt * WPITCH);
            const float4* ov = (const float4*)mO2;
            float acc[4] = {0.f, 0.f, 0.f, 0.f};
            #pragma unroll
            for (int i = 0; i < DIM / 4; i++) {
                float4 w = wr[i]; float4 o = ov[i];
                float a = acc[i & 3];
                a = fmaf(w.x, o.x, a); a = fmaf(w.y, o.y, a);
                a = fmaf(w.z, o.z, a); a = fmaf(w.w, o.w, a);
                acc[i & 3] = a;
            }
            if (active)
                d_hbuf[(size_t)r * DIM + tt] = (acc[0] + acc[1]) + (acc[2] + acc[3]);
        }
    }
}

// ---------------- K4: edge scatter out[dst] += norm * h[src] (warp per edge) ----------------
__global__ void k_edge(const int* __restrict__ adj, int E, float* __restrict__ out) {
    int widx = (blockIdx.x * blockDim.x + threadIdx.x) >> 5;
    int lane = threadIdx.x & 31;
    if (widx >= E) return;
    int s = adj[widx], d = adj[E + widx];
    float norm = rsqrtf(fmaxf(d_deg[s], 1e-12f)) * rsqrtf(fmaxf(d_deg[d], 1e-12f));
    const float* hr = d_hbuf + (size_t)s * DIM;
    float* orow = out + (size_t)d * DIM;
    #pragma unroll
    for (int j = lane; j < DIM; j += 32)
        atomicAdd(&orow[j], norm * hr[j]);
}

// ---------------- K5: self loop + PReLU ----------------
__global__ void k_final(const float* __restrict__ prelu, float* __restrict__ out) {
    int idx = blockIdx.x * blockDim.x + threadIdx.x;
    if (idx >= R_REG * DIM) return;
    int r = idx >> 7, j = idx & 127;
    float dis = rsqrtf(fmaxf(d_deg[r], 1e-12f));
    float val = out[idx] + dis * dis * d_hbuf[idx];
    out[idx] = val > 0.f ? val : prelu[j] * val;
}

// ---------------- launch ----------------
extern "C" void kernel_launch(void* const* d_in, const int* in_sizes, int n_in,
                              void* d_out, int out_size) {
    const float* x    = (const float*)d_in[0];
    const int*   zone = (const int*)d_in[1];
    const int*   adj  = (const int*)d_in[2];
    const float* S    = (const float*)d_in[3];
    const float* Wq   = (const float*)d_in[4];
    const float* bq   = (const float*)d_in[5];
    const float* Wk   = (const float*)d_in[6];
    const float* bk   = (const float*)d_in[7];
    const float* Wv   = (const float*)d_in[8];
    const float* bv   = (const float*)d_in[9];
    const float* Wo   = (const float*)d_in[10];
    const float* bo   = (const float*)d_in[11];
    const float* Wg   = (const float*)d_in[12];
    const float* bg   = (const float*)d_in[13];
    const float* prelu = (const float*)d_in[14];
    float* out = (float*)d_out;
    int N = in_sizes[0] / DIM;
    int E = in_sizes[2] / 2;

    // K0: init + histogram + fused scan + setup
    int nbI = (R_REG * DIM + 255) / 256;
    int nbH = (N + HIST_CHUNK - 1) / HIST_CHUNK;
    k_init_setup<<<nbI + nbH + 1, 256>>>(bg, out, S, Wq, bq, Wk, bk, zone, N, nbI, nbH);

    // K1: counting-sort scatter (4 pts/thread) + deg blocks
    int nbS = (N + 1023) / 1024;
    int nbD = (E + 255) / 256;
    k_sort<<<nbS + nbD, 256>>>(zone, adj, N, E, nbS);

    // K2: fused score+accumulate — single pass over x, ILP-4, clean steady-state loop
    k_accum<<<R_REG, 128>>>(x);

    // K3: epilogue — 4 regions per 512-thread block
    int smem_epi = (3 * DIM * WPITCH + EPI_SUBS * (NHEAD * DIM + 2 * DIM)) * (int)sizeof(float);
    cudaFuncSetAttribute(k_epilogue, cudaFuncAttributeMaxDynamicSharedMemorySize, smem_epi);
    int rpb = 16;
    k_epilogue<<<(R_REG + rpb - 1) / rpb, 512, smem_epi>>>(Wv, bv, Wo, bo, Wg, rpb);

    k_edge<<<(E * 32 + 255) / 256, 256>>>(adj, E, out);
    k_final<<<(R_REG * DIM + 255) / 256, 256>>>(prelu, out);
}

// round 13
// speedup vs baseline: 1.5306x; 1.0579x over previous
#include <cuda_runtime.h>
#include <math.h>

#define R_REG 2000
#define NHEAD 4
#define DIM   128
#define DH    32
#define NMAX  500000
#define WPITCH 132   // smem pitch (floats): lane stride ≡4 banks → conflict-free float4 phases
#define HIST_CHUNK 16384

// ---------------- scratch (device globals; no allocation allowed) ----------------
__device__ float d_q[DIM];                      // PMA seed query (flattened)
__device__ float d_A[NHEAD * DIM];              // folded score matrix (incl 1/sqrt(D))
__device__ float d_c[NHEAD];                    // folded score bias
__device__ int   d_hist[R_REG];                 // zeroed by fused scan after reading (replay-safe)
__device__ int   d_starts[R_REG + 1];
__device__ int   d_cursor[R_REG];
__device__ int   d_order[NMAX + 16];            // +16 pad so prefetch needs no bounds checks
__device__ int   d_tick;                        // last-block ticket for fused scan
__device__ __align__(16) float d_u[R_REG * NHEAD * DIM];  // normalized weighted sums of x
__device__ float d_flag[R_REG];                 // 1 if region nonempty
__device__ float d_hbuf[R_REG * DIM];           // GCN h = O @ Wg^T
__device__ float d_deg[R_REG];

// ---------------- K0: init + privatized histogram + fused exclusive scan + setup ----------------
__global__ void k_init_setup(const float* __restrict__ bg, float* __restrict__ out,
                             const float* __restrict__ S, const float* __restrict__ Wq,
                             const float* __restrict__ bq, const float* __restrict__ Wk,
                             const float* __restrict__ bk, const int* __restrict__ zone,
                             int N, int nbI, int nbH) {
    int t = threadIdx.x;
    int b = blockIdx.x;
    if (b < nbI) {
        int i = b * blockDim.x + t;
        if (i < R_REG * DIM) out[i] = bg[i & (DIM - 1)];
        if (i < R_REG) d_deg[i] = 1.0f;   // deg starts at 1 (self loop)
        if (b == 0 && t < 16) d_order[N + t] = 0;  // prefetch pad (valid index 0)
    } else if (b < nbI + nbH) {
        // privatized histogram: one smem pass per chunk, then sparse global flush
        __shared__ int hs[R_REG];
        __shared__ int isLast;
        for (int i = t; i < R_REG; i += 256) hs[i] = 0;
        __syncthreads();
        int base = (b - nbI) * HIST_CHUNK;
        int lim = min(HIST_CHUNK, N - base);
        for (int i = t; i < lim; i += 256) atomicAdd(&hs[zone[base + i]], 1);
        __syncthreads();
        for (int i = t; i < R_REG; i += 256) {
            int v = hs[i];
            if (v) atomicAdd(&d_hist[i], v);
        }
        // ---- last hist block performs the exclusive scan inline (saves a launch) ----
        if (t == 0) {
            __threadfence();
            isLast = (atomicAdd(&d_tick, 1) == nbH - 1) ? 1 : 0;
        }
        __syncthreads();
        if (isLast) {
            if (t == 0) { d_tick = 0; __threadfence(); }
            __shared__ int wsum[8];
            int sbase = t * 8;
            int vals[8]; int s = 0;
            #pragma unroll
            for (int i = 0; i < 8; i++) {
                int idx = sbase + i;
                int v = 0;
                if (idx < R_REG) { v = d_hist[idx]; d_hist[idx] = 0; }  // read + reset
                vals[i] = s; s += v;
            }
            int lane = t & 31, w = t >> 5;
            int inc = s;
            #pragma unroll
            for (int off = 1; off < 32; off <<= 1) {
                int o = __shfl_up_sync(0xffffffffu, inc, off);
                if (lane >= off) inc += o;
            }
            if (lane == 31) wsum[w] = inc;
            __syncthreads();
            if (t == 0) {
                int acc = 0;
                for (int i = 0; i < 8; i++) { int v = wsum[i]; wsum[i] = acc; acc += v; }
                d_starts[R_REG] = acc;
            }
            __syncthreads();
            int texcl = inc - s + wsum[w];
            #pragma unroll
            for (int i = 0; i < 8; i++) {
                int idx = sbase + i;
                if (idx < R_REG) {
                    int st = texcl + vals[i];
                    d_starts[idx] = st;
                    d_cursor[idx] = st;
                }
            }
        }
    } else {
        // ---- setup: q = Wq S + bq ; A = (q^T Wk)/sqrt(D) ----
        __shared__ float S_s[DIM];
        __shared__ float q_s[DIM];
        if (t < DIM) S_s[t] = S[t];
        __syncthreads();
        if (t < DIM) {
            float acc = bq[t];
            const float4* wrow = (const float4*)(Wq + t * DIM);
            const float4* s4 = (const float4*)S_s;
            #pragma unroll
            for (int i = 0; i < DIM / 4; i++) {
                float4 w = wrow[i]; float4 s = s4[i];
                acc = fmaf(w.x, s.x, acc); acc = fmaf(w.y, s.y, acc);
                acc = fmaf(w.z, s.z, acc); acc = fmaf(w.w, s.w, acc);
            }
            q_s[t] = acc;
            d_q[t] = acc;
        }
        __syncthreads();
        if (t < DIM) {
            const float invsq = 0.08838834764831845f;  // 1/sqrt(128)
            for (int h = 0; h < NHEAD; h++) {
                float a = 0.f;
                #pragma unroll 8
                for (int dh = 0; dh < DH; dh++)
                    a = fmaf(q_s[h * DH + dh], Wk[(h * DH + dh) * DIM + t], a);
                d_A[h * DIM + t] = a * invsq;
            }
            if (t < NHEAD) {
                float cc = 0.f;
                for (int dh = 0; dh < DH; dh++) cc = fmaf(q_s[t * DH + dh], bk[t * DH + dh], cc);
                d_c[t] = cc * invsq;
            }
        }
    }
}

// ---------------- K1: counting-sort scatter (4 pts/thread, int4 zone loads) + fused deg ----------------
__global__ void __launch_bounds__(256) k_sort(const int* __restrict__ zone,
                                              const int* __restrict__ adj,
                                              int N, int E, int nbS) {
    if ((int)blockIdx.x >= nbS) {
        int e = (blockIdx.x - nbS) * blockDim.x + threadIdx.x;
        if (e < E) atomicAdd(&d_deg[adj[E + e]], 1.0f);
        return;
    }
    int tid = blockIdx.x * blockDim.x + threadIdx.x;
    int base = tid * 4;
    if (base >= N) return;
    if (base + 3 < N) {
        int4 z = *(const int4*)(zone + base);   // 16B vector load
        // 4 independent atomic chains in flight
        int p0 = atomicAdd(&d_cursor[z.x], 1);
        int p1 = atomicAdd(&d_cursor[z.y], 1);
        int p2 = atomicAdd(&d_cursor[z.z], 1);
        int p3 = atomicAdd(&d_cursor[z.w], 1);
        d_order[p0] = base;
        d_order[p1] = base + 1;
        d_order[p2] = base + 2;
        d_order[p3] = base + 3;
    } else {
        for (int n = base; n < N; n++) {
            int pos = atomicAdd(&d_cursor[zone[n]], 1);
            d_order[pos] = n;
        }
    }
}

// 4-head warp reduction in 9 shfls; ALL lanes of 8-lane group g end with head-g's full sum
__device__ __forceinline__ float headred(float s0, float s1, float s2, float s3, int lane) {
    float o0 = __shfl_xor_sync(0xffffffffu, s0, 16);
    float o1 = __shfl_xor_sync(0xffffffffu, s1, 16);
    float o2 = __shfl_xor_sync(0xffffffffu, s2, 16);
    float o3 = __shfl_xor_sync(0xffffffffu, s3, 16);
    float t0, t1;
    if (lane < 16) { t0 = s0 + o0; t1 = s1 + o1; } else { t0 = s2 + o2; t1 = s3 + o3; }
    float p0 = __shfl_xor_sync(0xffffffffu, t0, 8);
    float p1 = __shfl_xor_sync(0xffffffffu, t1, 8);
    float v = ((lane & 8) == 0) ? (t0 + p0) : (t1 + p1);
    v += __shfl_xor_sync(0xffffffffu, v, 4);
    v += __shfl_xor_sync(0xffffffffu, v, 2);
    v += __shfl_xor_sync(0xffffffffu, v, 1);
    return v;
}

// ---------------- K2: single-pass score + weighted accumulation (x read ONCE) ----------------
// Steady-state loop has NO bounds checks or tail masking (main/tail split; d_order padded).
__global__ void __launch_bounds__(128) k_accum(const float* __restrict__ x) {
    int r = blockIdx.x;
    int t = threadIdx.x;
    int w = t >> 5, lane = t & 31;
    int start = d_starts[r], end = d_starts[r + 1];
    const float4* x4 = (const float4*)x;
    const float4* A4 = (const float4*)d_A;
    float4 A0 = A4[0 * 32 + lane], A1 = A4[1 * 32 + lane];
    float4 A2 = A4[2 * 32 + lane], A3 = A4[3 * 32 + lane];
    float cb = d_c[lane >> 3];   // head bias (head = lane>>3); v holds that head's sum
    float4 a0 = make_float4(0.f,0.f,0.f,0.f), a1 = a0, a2 = a0, a3 = a0;
    float dn0 = 0.f, dn1 = 0.f, dn2 = 0.f, dn3 = 0.f;
    #define DOT4(a, v) ((a).x*(v).x + (a).y*(v).y + (a).z*(v).z + (a).w*(v).w)
    int p = start + 4 * w;
    // unconditional preload (d_order padded by 16 zeroed entries)
    int n0 = __ldg(&d_order[p]);
    int n1 = __ldg(&d_order[p + 1]);
    int n2 = __ldg(&d_order[p + 2]);
    int n3 = __ldg(&d_order[p + 3]);
    #pragma unroll 1
    while (p + 4 <= end) {
        // 4 independent x-row gathers (2KB in flight per warp)
        float4 xv0 = __ldg(&x4[(size_t)n0 * 32 + lane]);
        float4 xv1 = __ldg(&x4[(size_t)n1 * 32 + lane]);
        float4 xv2 = __ldg(&x4[(size_t)n2 * 32 + lane]);
        float4 xv3 = __ldg(&x4[(size_t)n3 * 32 + lane]);
        // unguarded prefetch of next quad (pad-safe)
        int pn = p + 16;
        n0 = __ldg(&d_order[pn]);
        n1 = __ldg(&d_order[pn + 1]);
        n2 = __ldg(&d_order[pn + 2]);
        n3 = __ldg(&d_order[pn + 3]);
        // 4 interleaved score reductions (shfl latencies hide each other)
        float v0 = headred(DOT4(A0,xv0), DOT4(A1,xv0), DOT4(A2,xv0), DOT4(A3,xv0), lane);
        float v1 = headred(DOT4(A0,xv1), DOT4(A1,xv1), DOT4(A2,xv1), DOT4(A3,xv1), lane);
        float v2 = headred(DOT4(A0,xv2), DOT4(A1,xv2), DOT4(A2,xv2), DOT4(A3,xv2), lane);
        float v3 = headred(DOT4(A0,xv3), DOT4(A1,xv3), DOT4(A2,xv3), DOT4(A3,xv3), lane);
        float ev0 = __expf(v0 + cb);
        float ev1 = __expf(v1 + cb);
        float ev2 = __expf(v2 + cb);
        float ev3 = __expf(v3 + cb);
        float e00 = __shfl_sync(0xffffffffu, ev0, 0);
        float e01 = __shfl_sync(0xffffffffu, ev0, 8);
        float e02 = __shfl_sync(0xffffffffu, ev0, 16);
        float e03 = __shfl_sync(0xffffffffu, ev0, 24);
        float e10 = __shfl_sync(0xffffffffu, ev1, 0);
        float e11 = __shfl_sync(0xffffffffu, ev1, 8);
        float e12 = __shfl_sync(0xffffffffu, ev1, 16);
        float e13 = __shfl_sync(0xffffffffu, ev1, 24);
        float e20 = __shfl_sync(0xffffffffu, ev2, 0);
        float e21 = __shfl_sync(0xffffffffu, ev2, 8);
        float e22 = __shfl_sync(0xffffffffu, ev2, 16);
        float e23 = __shfl_sync(0xffffffffu, ev2, 24);
        float e30 = __shfl_sync(0xffffffffu, ev3, 0);
        float e31 = __shfl_sync(0xffffffffu, ev3, 8);
        float e32 = __shfl_sync(0xffffffffu, ev3, 16);
        float e33 = __shfl_sync(0xffffffffu, ev3, 24);
        a0.x = fmaf(e00, xv0.x, a0.x); a0.y = fmaf(e00, xv0.y, a0.y);
        a0.z = fmaf(e00, xv0.z, a0.z); a0.w = fmaf(e00, xv0.w, a0.w);
        a1.x = fmaf(e01, xv0.x, a1.x); a1.y = fmaf(e01, xv0.y, a1.y);
        a1.z = fmaf(e01, xv0.z, a1.z); a1.w = fmaf(e01, xv0.w, a1.w);
        a2.x = fmaf(e02, xv0.x, a2.x); a2.y = fmaf(e02, xv0.y, a2.y);
        a2.z = fmaf(e02, xv0.z, a2.z); a2.w = fmaf(e02, xv0.w, a2.w);
        a3.x = fmaf(e03, xv0.x, a3.x); a3.y = fmaf(e03, xv0.y, a3.y);
        a3.z = fmaf(e03, xv0.z, a3.z); a3.w = fmaf(e03, xv0.w, a3.w);
        dn0 += e00; dn1 += e01; dn2 += e02; dn3 += e03;
        a0.x = fmaf(e10, xv1.x, a0.x); a0.y = fmaf(e10, xv1.y, a0.y);
        a0.z = fmaf(e10, xv1.z, a0.z); a0.w = fmaf(e10, xv1.w, a0.w);
        a1.x = fmaf(e11, xv1.x, a1.x); a1.y = fmaf(e11, xv1.y, a1.y);
        a1.z = fmaf(e11, xv1.z, a1.z); a1.w = fmaf(e11, xv1.w, a1.w);
        a2.x = fmaf(e12, xv1.x, a2.x); a2.y = fmaf(e12, xv1.y, a2.y);
        a2.z = fmaf(e12, xv1.z, a2.z); a2.w = fmaf(e12, xv1.w, a2.w);
        a3.x = fmaf(e13, xv1.x, a3.x); a3.y = fmaf(e13, xv1.y, a3.y);
        a3.z = fmaf(e13, xv1.z, a3.z); a3.w = fmaf(e13, xv1.w, a3.w);
        dn0 += e10; dn1 += e11; dn2 += e12; dn3 += e13;
        a0.x = fmaf(e20, xv2.x, a0.x); a0.y = fmaf(e20, xv2.y, a0.y);
        a0.z = fmaf(e20, xv2.z, a0.z); a0.w = fmaf(e20, xv2.w, a0.w);
        a1.x = fmaf(e21, xv2.x, a1.x); a1.y = fmaf(e21, xv2.y, a1.y);
        a1.z = fmaf(e21, xv2.z, a1.z); a1.w = fmaf(e21, xv2.w, a1.w);
        a2.x = fmaf(e22, xv2.x, a2.x); a2.y = fmaf(e22, xv2.y, a2.y);
        a2.z = fmaf(e22, xv2.z, a2.z); a2.w = fmaf(e22, xv2.w, a2.w);
        a3.x = fmaf(e23, xv2.x, a3.x); a3.y = fmaf(e23, xv2.y, a3.y);
        a3.z = fmaf(e23, xv2.z, a3.z); a3.w = fmaf(e23, xv2.w, a3.w);
        dn0 += e20; dn1 += e21; dn2 += e22; dn3 += e23;
        a0.x = fmaf(e30, xv3.x, a0.x); a0.y = fmaf(e30, xv3.y, a0.y);
        a0.z = fmaf(e30, xv3.z, a0.z); a0.w = fmaf(e30, xv3.w, a0.w);
        a1.x = fmaf(e31, xv3.x, a1.x); a1.y = fmaf(e31, xv3.y, a1.y);
        a1.z = fmaf(e31, xv3.z, a1.z); a1.w = fmaf(e31, xv3.w, a1.w);
        a2.x = fmaf(e32, xv3.x, a2.x); a2.y = fmaf(e32, xv3.y, a2.y);
        a2.z = fmaf(e32, xv3.z, a2.z); a2.w = fmaf(e32, xv3.w, a2.w);
        a3.x = fmaf(e33, xv3.x, a3.x); a3.y = fmaf(e33, xv3.y, a3.y);
        a3.z = fmaf(e33, xv3.z, a3.z); a3.w = fmaf(e33, xv3.w, a3.w);
        dn0 += e30; dn1 += e31; dn2 += e32; dn3 += e33;
        p = pn;
    }
    // tail: up to 3 leftover points for this warp
    for (int q = p; q < end && q < p + 4; q++) {
        int n = __ldg(&d_order[q]);
        float4 xv = __ldg(&x4[(size_t)n * 32 + lane]);
        float v = headred(DOT4(A0,xv), DOT4(A1,xv), DOT4(A2,xv), DOT4(A3,xv), lane);
        float ev = __expf(v + cb);
        float e0 = __shfl_sync(0xffffffffu, ev, 0);
        float e1 = __shfl_sync(0xffffffffu, ev, 8);
        float e2 = __shfl_sync(0xffffffffu, ev, 16);
        float e3 = __shfl_sync(0xffffffffu, ev, 24);
        a0.x = fmaf(e0, xv.x, a0.x); a0.y = fmaf(e0, xv.y, a0.y);
        a0.z = fmaf(e0, xv.z, a0.z); a0.w = fmaf(e0, xv.w, a0.w);
        a1.x = fmaf(e1, xv.x, a1.x); a1.y = fmaf(e1, xv.y, a1.y);
        a1.z = fmaf(e1, xv.z, a1.z); a1.w = fmaf(e1, xv.w, a1.w);
        a2.x = fmaf(e2, xv.x, a2.x); a2.y = fmaf(e2, xv.y, a2.y);
        a2.z = fmaf(e2, xv.z, a2.z); a2.w = fmaf(e2, xv.w, a2.w);
        a3.x = fmaf(e3, xv.x, a3.x); a3.y = fmaf(e3, xv.y, a3.y);
        a3.z = fmaf(e3, xv.z, a3.z); a3.w = fmaf(e3, xv.w, a3.w);
        dn0 += e0; dn1 += e1; dn2 += e2; dn3 += e3;
    }
    #undef DOT4
    // cross-warp combine in smem: part[warp][head][lane] (float4 = dims 4*lane..4*lane+3)
    __shared__ float4 part[4][4][32];
    __shared__ float pdn[4][4];
    part[w][0][lane] = a0; part[w][1][lane] = a1;
    part[w][2][lane] = a2; part[w][3][lane] = a3;
    if (lane == 0) { pdn[w][0] = dn0; pdn[w][1] = dn1; pdn[w][2] = dn2; pdn[w][3] = dn3; }
    __syncthreads();
    // thread t = (h=w, lane) finalizes head w
    int h = w;
    float4 s0 = part[0][h][lane], s1 = part[1][h][lane];
    float4 s2 = part[2][h][lane], s3 = part[3][h][lane];
    float4 u;
    u.x = s0.x + s1.x + s2.x + s3.x;
    u.y = s0.y + s1.y + s2.y + s3.y;
    u.z = s0.z + s1.z + s2.z + s3.z;
    u.w = s0.w + s1.w + s2.w + s3.w;
    float dn = pdn[0][h] + pdn[1][h] + pdn[2][h] + pdn[3][h];
    float inv = dn > 0.f ? 1.0f / dn : 0.f;
    u.x *= inv; u.y *= inv; u.z *= inv; u.w *= inv;
    ((float4*)d_u)[(size_t)r * 128 + h * 32 + lane] = u;
    if (t == 0) d_flag[r] = (end > start) ? 1.0f : 0.0f;
}

// ---------------- K3: batched epilogue — each thread applies its weight row to 4 regions ----------------
// Block: 512 threads = 4 groups of 128; group g handles regions [blk*16 + 4g, +4).
// Weight float4 read ONCE serves 4 regions (4x less smem traffic than per-region matvec).
// Region vectors come in as 16B broadcast loads (u from global/L1, O from smem).
// 2000 = 125 blocks * 16 regions exactly -> no bounds checks.
__global__ void __launch_bounds__(512) k_epilogue(
        const float* __restrict__ Wv, const float* __restrict__ bv,
        const float* __restrict__ Wo, const float* __restrict__ bo,
        const float* __restrict__ Wg) {
    extern __shared__ float sm[];
    float* Wv_s = sm;
    float* Wo_s = Wv_s + DIM * WPITCH;
    float* Wg_s = Wo_s + DIM * WPITCH;
    float* O_s  = Wg_s + DIM * WPITCH;   // 16 regions x 128
    float* O2_s = O_s + 16 * DIM;        // 16 regions x 128
    int t = threadIdx.x;
    int sub = t >> 7;      // group id (0..3)
    int tt = t & 127;      // output element / weight row
    int h = tt >> 5;       // head for stage 1
    for (int idx = t; idx < DIM * DIM / 4; idx += 512) {
        int row = idx >> 5, col4 = idx & 31;
        float4 v0 = ((const float4*)Wv)[idx];
        float4 v1 = ((const float4*)Wo)[idx];
        float4 v2 = ((const float4*)Wg)[idx];
        *(float4*)(Wv_s + row * WPITCH + col4 * 4) = v0;
        *(float4*)(Wo_s + row * WPITCH + col4 * 4) = v1;
        *(float4*)(Wg_s + row * WPITCH + col4 * 4) = v2;
    }
    float qv = d_q[tt], bvv = bv[tt], bov = bo[tt];
    int rbase = blockIdx.x * 16 + sub * 4;       // 4 consecutive regions for this group
    __syncthreads();                             // weights visible to all
    int slot = sub * 4;                          // O_s slot base for this group
    // ---- stage 1: O_g = q + Wv . u_g + flag_g*bv   (4 regions per weight read) ----
    {
        const float4* wr = (const float4*)(Wv_s + tt * WPITCH);
        const float4* u0 = (const float4*)(d_u + (size_t)(rbase + 0) * 512 + h * 128);
        const float4* u1 = (const float4*)(d_u + (size_t)(rbase + 1) * 512 + h * 128);
        const float4* u2 = (const float4*)(d_u + (size_t)(rbase + 2) * 512 + h * 128);
        const float4* u3 = (const float4*)(d_u + (size_t)(rbase + 3) * 512 + h * 128);
        float a0 = 0.f, a1 = 0.f, a2 = 0.f, a3 = 0.f;
        #pragma unroll
        for (int i = 0; i < DIM / 4; i++) {
            float4 w = wr[i];
            float4 v0 = __ldg(&u0[i]);
            float4 v1 = __ldg(&u1[i]);
            float4 v2 = __ldg(&u2[i]);
            float4 v3 = __ldg(&u3[i]);
            a0 = fmaf(w.x, v0.x, a0); a0 = fmaf(w.y, v0.y, a0);
            a0 = fmaf(w.z, v0.z, a0); a0 = fmaf(w.w, v0.w, a0);
            a1 = fmaf(w.x, v1.x, a1); a1 = fmaf(w.y, v1.y, a1);
            a1 = fmaf(w.z, v1.z, a1); a1 = fmaf(w.w, v1.w, a1);
            a2 = fmaf(w.x, v2.x, a2); a2 = fmaf(w.y, v2.y, a2);
            a2 = fmaf(w.z, v2.z, a2); a2 = fmaf(w.w, v2.w, a2);
            a3 = fmaf(w.x, v3.x, a3); a3 = fmaf(w.y, v3.y, a3);
            a3 = fmaf(w.z, v3.z, a3); a3 = fmaf(w.w, v3.w, a3);
        }
        O_s[(slot + 0) * DIM + tt] = qv + a0 + d_flag[rbase + 0] * bvv;
        O_s[(slot + 1) * DIM + tt] = qv + a1 + d_flag[rbase + 1] * bvv;
        O_s[(slot + 2) * DIM + tt] = qv + a2 + d_flag[rbase + 2] * bvv;
        O_s[(slot + 3) * DIM + tt] = qv + a3 + d_flag[rbase + 3] * bvv;
    }
    asm volatile("bar.sync %0, %1;" :: "r"(sub + 1), "r"(128) : "memory");
    // ---- stage 2: O2_g = O_g + relu(Wo . O_g + bo) ----
    {
        const float4* wr = (const float4*)(Wo_s + tt * WPITCH);
        const float4* o0 = (const float4*)(O_s + (slot + 0) * DIM);
        const float4* o1 = (const float4*)(O_s + (slot + 1) * DIM);
        const float4* o2 = (const float4*)(O_s + (slot + 2) * DIM);
        const float4* o3 = (const float4*)(O_s + (slot + 3) * DIM);
        float a0 = bov, a1 = bov, a2 = bov, a3 = bov;
        #pragma unroll
        for (int i = 0; i < DIM / 4; i++) {
            float4 w = wr[i];
            float4 v0 = o0[i];
            float4 v1 = o1[i];
            float4 v2 = o2[i];
            float4 v3 = o3[i];
            a0 = fmaf(w.x, v0.x, a0); a0 = fmaf(w.y, v0.y, a0);
            a0 = fmaf(w.z, v0.z, a0); a0 = fmaf(w.w, v0.w, a0);
            a1 = fmaf(w.x, v1.x, a1); a1 = fmaf(w.y, v1.y, a1);
            a1 = fmaf(w.z, v1.z, a1); a1 = fmaf(w.w, v1.w, a1);
            a2 = fmaf(w.x, v2.x, a2); a2 = fmaf(w.y, v2.y, a2);
            a2 = fmaf(w.z, v2.z, a2); a2 = fmaf(w.w, v2.w, a2);
            a3 = fmaf(w.x, v3.x, a3); a3 = fmaf(w.y, v3.y, a3);
            a3 = fmaf(w.z, v3.z, a3); a3 = fmaf(w.w, v3.w, a3);
        }
        O2_s[(slot + 0) * DIM + tt] = O_s[(slot + 0) * DIM + tt] + fmaxf(a0, 0.f);
        O2_s[(slot + 1) * DIM + tt] = O_s[(slot + 1) * DIM + tt] + fmaxf(a1, 0.f);
        O2_s[(slot + 2) * DIM + tt] = O_s[(slot + 2) * DIM + tt] + fmaxf(a2, 0.f);
        O2_s[(slot + 3) * DIM + tt] = O_s[(slot + 3) * DIM + tt] + fmaxf(a3, 0.f);
    }
    asm volatile("bar.sync %0, %1;" :: "r"(sub + 1), "r"(128) : "memory");
    // ---- stage 3: h_g = Wg . O2_g -> global ----
    {
        const float4* wr = (const float4*)(Wg_s + tt * WPITCH);
        const float4* o0 = (const float4*)(O2_s + (slot + 0) * DIM);
        const float4* o1 = (const float4*)(O2_s + (slot + 1) * DIM);
        const float4* o2 = (const float4*)(O2_s + (slot + 2) * DIM);
        const float4* o3 = (const float4*)(O2_s + (slot + 3) * DIM);
        float a0 = 0.f, a1 = 0.f, a2 = 0.f, a3 = 0.f;
        #pragma unroll
        for (int i = 0; i < DIM / 4; i++) {
            float4 w = wr[i];
            float4 v0 = o0[i];
            float4 v1 = o1[i];
            float4 v2 = o2[i];
            float4 v3 = o3[i];
            a0 = fmaf(w.x, v0.x, a0); a0 = fmaf(w.y, v0.y, a0);
            a0 = fmaf(w.z, v0.z, a0); a0 = fmaf(w.w, v0.w, a0);
            a1 = fmaf(w.x, v1.x, a1); a1 = fmaf(w.y, v1.y, a1);
            a1 = fmaf(w.z, v1.z, a1); a1 = fmaf(w.w, v1.w, a1);
            a2 = fmaf(w.x, v2.x, a2); a2 = fmaf(w.y, v2.y, a2);
            a2 = fmaf(w.z, v2.z, a2); a2 = fmaf(w.w, v2.w, a2);
            a3 = fmaf(w.x, v3.x, a3); a3 = fmaf(w.y, v3.y, a3);
            a3 = fmaf(w.z, v3.z, a3); a3 = fmaf(w.w, v3.w, a3);
        }
        d_hbuf[(size_t)(rbase + 0) * DIM + tt] = a0;
        d_hbuf[(size_t)(rbase + 1) * DIM + tt] = a1;
        d_hbuf[(size_t)(rbase + 2) * DIM + tt] = a2;
        d_hbuf[(size_t)(rbase + 3) * DIM + tt] = a3;
    }
}

// ---------------- K4: edge scatter out[dst] += norm * h[src] (warp per edge) ----------------
__global__ void k_edge(const int* __restrict__ adj, int E, float* __restrict__ out) {
    int widx = (blockIdx.x * blockDim.x + threadIdx.x) >> 5;
    int lane = threadIdx.x & 31;
    if (widx >= E) return;
    int s = adj[widx], d = adj[E + widx];
    float norm = rsqrtf(fmaxf(d_deg[s], 1e-12f)) * rsqrtf(fmaxf(d_deg[d], 1e-12f));
    const float* hr = d_hbuf + (size_t)s * DIM;
    float* orow = out + (size_t)d * DIM;
    #pragma unroll
    for (int j = lane; j < DIM; j += 32)
        atomicAdd(&orow[j], norm * hr[j]);
}

// ---------------- K5: self loop + PReLU ----------------
__global__ void k_final(const float* __restrict__ prelu, float* __restrict__ out) {
    int idx = blockIdx.x * blockDim.x + threadIdx.x;
    if (idx >= R_REG * DIM) return;
    int r = idx >> 7, j = idx & 127;
    float dis = rsqrtf(fmaxf(d_deg[r], 1e-12f));
    float val = out[idx] + dis * dis * d_hbuf[idx];
    out[idx] = val > 0.f ? val : prelu[j] * val;
}

// ---------------- launch ----------------
extern "C" void kernel_launch(void* const* d_in, const int* in_sizes, int n_in,
                              void* d_out, int out_size) {
    const float* x    = (const float*)d_in[0];
    const int*   zone = (const int*)d_in[1];
    const int*   adj  = (const int*)d_in[2];
    const float* S    = (const float*)d_in[3];
    const float* Wq   = (const float*)d_in[4];
    const float* bq   = (const float*)d_in[5];
    const float* Wk   = (const float*)d_in[6];
    const float* bk   = (const float*)d_in[7];
    const float* Wv   = (const float*)d_in[8];
    const float* bv   = (const float*)d_in[9];
    const float* Wo   = (const float*)d_in[10];
    const float* bo   = (const float*)d_in[11];
    const float* Wg   = (const float*)d_in[12];
    const float* bg   = (const float*)d_in[13];
    const float* prelu = (const float*)d_in[14];
    float* out = (float*)d_out;
    int N = in_sizes[0] / DIM;
    int E = in_sizes[2] / 2;

    // K0: init + histogram + fused scan + setup
    int nbI = (R_REG * DIM + 255) / 256;
    int nbH = (N + HIST_CHUNK - 1) / HIST_CHUNK;
    k_init_setup<<<nbI + nbH + 1, 256>>>(bg, out, S, Wq, bq, Wk, bk, zone, N, nbI, nbH);

    // K1: counting-sort scatter (4 pts/thread) + deg blocks
    int nbS = (N + 1023) / 1024;
    int nbD = (E + 255) / 256;
    k_sort<<<nbS + nbD, 256>>>(zone, adj, N, E, nbS);

    // K2: fused score+accumulate — single pass over x, ILP-4, clean steady-state loop
    k_accum<<<R_REG, 128>>>(x);

    // K3: batched epilogue — 16 regions per 512-thread block, weight reads shared 4x
    int smem_epi = (3 * DIM * WPITCH + 32 * DIM) * (int)sizeof(float);
    cudaFuncSetAttribute(k_epilogue, cudaFuncAttributeMaxDynamicSharedMemorySize, smem_epi);
    k_epilogue<<<R_REG / 16, 512, smem_epi>>>(Wv, bv, Wo, bo, Wg);

    k_edge<<<(E * 32 + 255) / 256, 256>>>(adj, E, out);
    k_final<<<(R_REG * DIM + 255) / 256, 256>>>(prelu, out);
}

// round 16
// speedup vs baseline: 1.5335x; 1.0019x over previous
#include <cuda_runtime.h>
#include <math.h>

#define R_REG 2000
#define NHEAD 4
#define DIM   128
#define DH    32
#define NMAX  500000
#define WPITCH 132   // smem pitch (floats): lane stride ≡4 banks → conflict-free float4 phases
#define HIST_CHUNK 16384
#define EPI_G 8      // regions per thread-group in epilogue
#define ACC_BLOCKS 740   // 148 SMs * 5 resident blocks (96 regs, 128 thr)

// ---------------- scratch (device globals; no allocation allowed) ----------------
__device__ float d_q[DIM];                      // PMA seed query (flattened)
__device__ float d_A[NHEAD * DIM];              // folded score matrix (incl 1/sqrt(D))
__device__ float d_c[NHEAD];                    // folded score bias
__device__ int   d_hist[R_REG];                 // zeroed by fused scan after reading (replay-safe)
__device__ int   d_starts[R_REG + 1];
__device__ int   d_cursor[R_REG];
__device__ int   d_order[NMAX + 16];            // +16 pad so prefetch needs no bounds checks
__device__ int   d_tick;                        // last-block ticket for fused scan
__device__ int   d_rctr;                        // dynamic region counter for k_accum
__device__ __align__(16) float d_u[R_REG * NHEAD * DIM];  // normalized weighted sums of x
__device__ float d_flag[R_REG];                 // 1 if region nonempty
__device__ float d_hbuf[R_REG * DIM];           // GCN h = O @ Wg^T
__device__ float d_deg[R_REG];

// ---------------- K0: init + privatized histogram + fused exclusive scan + setup ----------------
__global__ void k_init_setup(const float* __restrict__ bg, float* __restrict__ out,
                             const float* __restrict__ S, const float* __restrict__ Wq,
                             const float* __restrict__ bq, const float* __restrict__ Wk,
                             const float* __restrict__ bk, const int* __restrict__ zone,
                             int N, int nbI, int nbH) {
    int t = threadIdx.x;
    int b = blockIdx.x;
    if (b < nbI) {
        int i = b * blockDim.x + t;
        if (i < R_REG * DIM) out[i] = bg[i & (DIM - 1)];
        if (i < R_REG) d_deg[i] = 1.0f;   // deg starts at 1 (self loop)
        if (b == 0 && t < 16) d_order[N + t] = 0;  // prefetch pad (valid index 0)
        if (b == 0 && t == 0) d_rctr = 0;          // reset dynamic counter (replay-safe)
    } else if (b < nbI + nbH) {
        // privatized histogram: one smem pass per chunk, then sparse global flush
        __shared__ int hs[R_REG];
        __shared__ int isLast;
        for (int i = t; i < R_REG; i += 256) hs[i] = 0;
        __syncthreads();
        int base = (b - nbI) * HIST_CHUNK;
        int lim = min(HIST_CHUNK, N - base);
        for (int i = t; i < lim; i += 256) atomicAdd(&hs[zone[base + i]], 1);
        __syncthreads();
        for (int i = t; i < R_REG; i += 256) {
            int v = hs[i];
            if (v) atomicAdd(&d_hist[i], v);
        }
        // ---- last hist block performs the exclusive scan inline (saves a launch) ----
        if (t == 0) {
            __threadfence();
            isLast = (atomicAdd(&d_tick, 1) == nbH - 1) ? 1 : 0;
        }
        __syncthreads();
        if (isLast) {
            if (t == 0) { d_tick = 0; __threadfence(); }
            __shared__ int wsum[8];
            int sbase = t * 8;
            int vals[8]; int s = 0;
            #pragma unroll
            for (int i = 0; i < 8; i++) {
                int idx = sbase + i;
                int v = 0;
                if (idx < R_REG) { v = d_hist[idx]; d_hist[idx] = 0; }  // read + reset
                vals[i] = s; s += v;
            }
            int lane = t & 31, w = t >> 5;
            int inc = s;
            #pragma unroll
            for (int off = 1; off < 32; off <<= 1) {
                int o = __shfl_up_sync(0xffffffffu, inc, off);
                if (lane >= off) inc += o;
            }
            if (lane == 31) wsum[w] = inc;
            __syncthreads();
            if (t == 0) {
                int acc = 0;
                for (int i = 0; i < 8; i++) { int v = wsum[i]; wsum[i] = acc; acc += v; }
                d_starts[R_REG] = acc;
            }
            __syncthreads();
            int texcl = inc - s + wsum[w];
            #pragma unroll
            for (int i = 0; i < 8; i++) {
                int idx = sbase + i;
                if (idx < R_REG) {
                    int st = texcl + vals[i];
                    d_starts[idx] = st;
                    d_cursor[idx] = st;
                }
            }
        }
    } else {
        // ---- setup: q = Wq S + bq ; A = (q^T Wk)/sqrt(D) ----
        __shared__ float S_s[DIM];
        __shared__ float q_s[DIM];
        if (t < DIM) S_s[t] = S[t];
        __syncthreads();
        if (t < DIM) {
            float acc = bq[t];
            const float4* wrow = (const float4*)(Wq + t * DIM);
            const float4* s4 = (const float4*)S_s;
            #pragma unroll
            for (int i = 0; i < DIM / 4; i++) {
                float4 w = wrow[i]; float4 s = s4[i];
                acc = fmaf(w.x, s.x, acc); acc = fmaf(w.y, s.y, acc);
                acc = fmaf(w.z, s.z, acc); acc = fmaf(w.w, s.w, acc);
            }
            q_s[t] = acc;
            d_q[t] = acc;
        }
        __syncthreads();
        if (t < DIM) {
            const float invsq = 0.08838834764831845f;  // 1/sqrt(128)
            for (int h = 0; h < NHEAD; h++) {
                float a = 0.f;
                #pragma unroll 8
                for (int dh = 0; dh < DH; dh++)
                    a = fmaf(q_s[h * DH + dh], Wk[(h * DH + dh) * DIM + t], a);
                d_A[h * DIM + t] = a * invsq;
            }
            if (t < NHEAD) {
                float cc = 0.f;
                for (int dh = 0; dh < DH; dh++) cc = fmaf(q_s[t * DH + dh], bk[t * DH + dh], cc);
                d_c[t] = cc * invsq;
            }
        }
    }
}

// ---------------- K1: counting-sort scatter (4 pts/thread, int4 zone loads) + fused deg ----------------
__global__ void __launch_bounds__(256) k_sort(const int* __restrict__ zone,
                                              const int* __restrict__ adj,
                                              int N, int E, int nbS) {
    if ((int)blockIdx.x >= nbS) {
        int e = (blockIdx.x - nbS) * blockDim.x + threadIdx.x;
        if (e < E) atomicAdd(&d_deg[adj[E + e]], 1.0f);
        return;
    }
    int tid = blockIdx.x * blockDim.x + threadIdx.x;
    int base = tid * 4;
    if (base >= N) return;
    if (base + 3 < N) {
        int4 z = *(const int4*)(zone + base);   // 16B vector load
        // 4 independent atomic chains in flight
        int p0 = atomicAdd(&d_cursor[z.x], 1);
        int p1 = atomicAdd(&d_cursor[z.y], 1);
        int p2 = atomicAdd(&d_cursor[z.z], 1);
        int p3 = atomicAdd(&d_cursor[z.w], 1);
        d_order[p0] = base;
        d_order[p1] = base + 1;
        d_order[p2] = base + 2;
        d_order[p3] = base + 3;
    } else {
        for (int n = base; n < N; n++) {
            int pos = atomicAdd(&d_cursor[zone[n]], 1);
            d_order[pos] = n;
        }
    }
}

// 4-head warp reduction in 9 shfls; ALL lanes of 8-lane group g end with head-g's full sum
__device__ __forceinline__ float headred(float s0, float s1, float s2, float s3, int lane) {
    float o0 = __shfl_xor_sync(0xffffffffu, s0, 16);
    float o1 = __shfl_xor_sync(0xffffffffu, s1, 16);
    float o2 = __shfl_xor_sync(0xffffffffu, s2, 16);
    float o3 = __shfl_xor_sync(0xffffffffu, s3, 16);
    float t0, t1;
    if (lane < 16) { t0 = s0 + o0; t1 = s1 + o1; } else { t0 = s2 + o2; t1 = s3 + o3; }
    float p0 = __shfl_xor_sync(0xffffffffu, t0, 8);
    float p1 = __shfl_xor_sync(0xffffffffu, t1, 8);
    float v = ((lane & 8) == 0) ? (t0 + p0) : (t1 + p1);
    v += __shfl_xor_sync(0xffffffffu, v, 4);
    v += __shfl_xor_sync(0xffffffffu, v, 2);
    v += __shfl_xor_sync(0xffffffffu, v, 1);
    return v;
}

// ---------------- K2: persistent single-pass score + weighted accumulation ----------------
// 740 resident blocks pull regions off a global counter (no wave quantization, no straggler tail).
__global__ void __launch_bounds__(128) k_accum(const float* __restrict__ x) {
    int t = threadIdx.x;
    int w = t >> 5, lane = t & 31;
    const float4* x4 = (const float4*)x;
    const float4* A4 = (const float4*)d_A;
    float4 A0 = A4[0 * 32 + lane], A1 = A4[1 * 32 + lane];
    float4 A2 = A4[2 * 32 + lane], A3 = A4[3 * 32 + lane];
    float cb = d_c[lane >> 3];   // head bias (head = lane>>3); v holds that head's sum
    __shared__ float4 part[4][4][32];
    __shared__ float pdn[4][4];
    __shared__ int sreg;
    #define DOT4(a, v) ((a).x*(v).x + (a).y*(v).y + (a).z*(v).z + (a).w*(v).w)
    while (true) {
        if (t == 0) sreg = atomicAdd(&d_rctr, 1);
        __syncthreads();
        int r = sreg;
        if (r >= R_REG) break;
        int start = d_starts[r], end = d_starts[r + 1];
        float4 a0 = make_float4(0.f,0.f,0.f,0.f), a1 = a0, a2 = a0, a3 = a0;
        float dn0 = 0.f, dn1 = 0.f, dn2 = 0.f, dn3 = 0.f;
        int p = start + 4 * w;
        // unconditional preload (d_order padded by 16 zeroed entries)
        int n0 = __ldg(&d_order[p]);
        int n1 = __ldg(&d_order[p + 1]);
        int n2 = __ldg(&d_order[p + 2]);
        int n3 = __ldg(&d_order[p + 3]);
        #pragma unroll 1
        while (p + 4 <= end) {
            // 4 independent x-row gathers (2KB in flight per warp)
            float4 xv0 = __ldg(&x4[(size_t)n0 * 32 + lane]);
            float4 xv1 = __ldg(&x4[(size_t)n1 * 32 + lane]);
            float4 xv2 = __ldg(&x4[(size_t)n2 * 32 + lane]);
            float4 xv3 = __ldg(&x4[(size_t)n3 * 32 + lane]);
            // unguarded prefetch of next quad (pad-safe)
            int pn = p + 16;
            n0 = __ldg(&d_order[pn]);
            n1 = __ldg(&d_order[pn + 1]);
            n2 = __ldg(&d_order[pn + 2]);
            n3 = __ldg(&d_order[pn + 3]);
            // 4 interleaved score reductions (shfl latencies hide each other)
            float v0 = headred(DOT4(A0,xv0), DOT4(A1,xv0), DOT4(A2,xv0), DOT4(A3,xv0), lane);
            float v1 = headred(DOT4(A0,xv1), DOT4(A1,xv1), DOT4(A2,xv1), DOT4(A3,xv1), lane);
            float v2 = headred(DOT4(A0,xv2), DOT4(A1,xv2), DOT4(A2,xv2), DOT4(A3,xv2), lane);
            float v3 = headred(DOT4(A0,xv3), DOT4(A1,xv3), DOT4(A2,xv3), DOT4(A3,xv3), lane);
            float ev0 = __expf(v0 + cb);
            float ev1 = __expf(v1 + cb);
            float ev2 = __expf(v2 + cb);
            float ev3 = __expf(v3 + cb);
            float e00 = __shfl_sync(0xffffffffu, ev0, 0);
            float e01 = __shfl_sync(0xffffffffu, ev0, 8);
            float e02 = __shfl_sync(0xffffffffu, ev0, 16);
            float e03 = __shfl_sync(0xffffffffu, ev0, 24);
            float e10 = __shfl_sync(0xffffffffu, ev1, 0);
            float e11 = __shfl_sync(0xffffffffu, ev1, 8);
            float e12 = __shfl_sync(0xffffffffu, ev1, 16);
            float e13 = __shfl_sync(0xffffffffu, ev1, 24);
            float e20 = __shfl_sync(0xffffffffu, ev2, 0);
            float e21 = __shfl_sync(0xffffffffu, ev2, 8);
            float e22 = __shfl_sync(0xffffffffu, ev2, 16);
            float e23 = __shfl_sync(0xffffffffu, ev2, 24);
            float e30 = __shfl_sync(0xffffffffu, ev3, 0);
            float e31 = __shfl_sync(0xffffffffu, ev3, 8);
            float e32 = __shfl_sync(0xffffffffu, ev3, 16);
            float e33 = __shfl_sync(0xffffffffu, ev3, 24);
            a0.x = fmaf(e00, xv0.x, a0.x); a0.y = fmaf(e00, xv0.y, a0.y);
            a0.z = fmaf(e00, xv0.z, a0.z); a0.w = fmaf(e00, xv0.w, a0.w);
            a1.x = fmaf(e01, xv0.x, a1.x); a1.y = fmaf(e01, xv0.y, a1.y);
            a1.z = fmaf(e01, xv0.z, a1.z); a1.w = fmaf(e01, xv0.w, a1.w);
            a2.x = fmaf(e02, xv0.x, a2.x); a2.y = fmaf(e02, xv0.y, a2.y);
            a2.z = fmaf(e02, xv0.z, a2.z); a2.w = fmaf(e02, xv0.w, a2.w);
            a3.x = fmaf(e03, xv0.x, a3.x); a3.y = fmaf(e03, xv0.y, a3.y);
            a3.z = fmaf(e03, xv0.z, a3.z); a3.w = fmaf(e03, xv0.w, a3.w);
            dn0 += e00; dn1 += e01; dn2 += e02; dn3 += e03;
            a0.x = fmaf(e10, xv1.x, a0.x); a0.y = fmaf(e10, xv1.y, a0.y);
            a0.z = fmaf(e10, xv1.z, a0.z); a0.w = fmaf(e10, xv1.w, a0.w);
            a1.x = fmaf(e11, xv1.x, a1.x); a1.y = fmaf(e11, xv1.y, a1.y);
            a1.z = fmaf(e11, xv1.z, a1.z); a1.w = fmaf(e11, xv1.w, a1.w);
            a2.x = fmaf(e12, xv1.x, a2.x); a2.y = fmaf(e12, xv1.y, a2.y);
            a2.z = fmaf(e12, xv1.z, a2.z); a2.w = fmaf(e12, xv1.w, a2.w);
            a3.x = fmaf(e13, xv1.x, a3.x); a3.y = fmaf(e13, xv1.y, a3.y);
            a3.z = fmaf(e13, xv1.z, a3.z); a3.w = fmaf(e13, xv1.w, a3.w);
            dn0 += e10; dn1 += e11; dn2 += e12; dn3 += e13;
            a0.x = fmaf(e20, xv2.x, a0.x); a0.y = fmaf(e20, xv2.y, a0.y);
            a0.z = fmaf(e20, xv2.z, a0.z); a0.w = fmaf(e20, xv2.w, a0.w);
            a1.x = fmaf(e21, xv2.x, a1.x); a1.y = fmaf(e21, xv2.y, a1.y);
            a1.z = fmaf(e21, xv2.z, a1.z); a1.w = fmaf(e21, xv2.w, a1.w);
            a2.x = fmaf(e22, xv2.x, a2.x); a2.y = fmaf(e22, xv2.y, a2.y);
            a2.z = fmaf(e22, xv2.z, a2.z); a2.w = fmaf(e22, xv2.w, a2.w);
            a3.x = fmaf(e23, xv2.x, a3.x); a3.y = fmaf(e23, xv2.y, a3.y);
            a3.z = fmaf(e23, xv2.z, a3.z); a3.w = fmaf(e23, xv2.w, a3.w);
            dn0 += e20; dn1 += e21; dn2 += e22; dn3 += e23;
            a0.x = fmaf(e30, xv3.x, a0.x); a0.y = fmaf(e30, xv3.y, a0.y);
            a0.z = fmaf(e30, xv3.z, a0.z); a0.w = fmaf(e30, xv3.w, a0.w);
            a1.x = fmaf(e31, xv3.x, a1.x); a1.y = fmaf(e31, xv3.y, a1.y);
            a1.z = fmaf(e31, xv3.z, a1.z); a1.w = fmaf(e31, xv3.w, a1.w);
            a2.x = fmaf(e32, xv3.x, a2.x); a2.y = fmaf(e32, xv3.y, a2.y);
            a2.z = fmaf(e32, xv3.z, a2.z); a2.w = fmaf(e32, xv3.w, a2.w);
            a3.x = fmaf(e33, xv3.x, a3.x); a3.y = fmaf(e33, xv3.y, a3.y);
            a3.z = fmaf(e33, xv3.z, a3.z); a3.w = fmaf(e33, xv3.w, a3.w);
            dn0 += e30; dn1 += e31; dn2 += e32; dn3 += e33;
            p = pn;
        }
        // tail: up to 3 leftover points for this warp
        for (int q = p; q < end && q < p + 4; q++) {
            int n = __ldg(&d_order[q]);
            float4 xv = __ldg(&x4[(size_t)n * 32 + lane]);
            float v = headred(DOT4(A0,xv), DOT4(A1,xv), DOT4(A2,xv), DOT4(A3,xv), lane);
            float ev = __expf(v + cb);
            float e0 = __shfl_sync(0xffffffffu, ev, 0);
            float e1 = __shfl_sync(0xffffffffu, ev, 8);
            float e2 = __shfl_sync(0xffffffffu, ev, 16);
            float e3 = __shfl_sync(0xffffffffu, ev, 24);
            a0.x = fmaf(e0, xv.x, a0.x); a0.y = fmaf(e0, xv.y, a0.y);
            a0.z = fmaf(e0, xv.z, a0.z); a0.w = fmaf(e0, xv.w, a0.w);
            a1.x = fmaf(e1, xv.x, a1.x); a1.y = fmaf(e1, xv.y, a1.y);
            a1.z = fmaf(e1, xv.z, a1.z); a1.w = fmaf(e1, xv.w, a1.w);
            a2.x = fmaf(e2, xv.x, a2.x); a2.y = fmaf(e2, xv.y, a2.y);
            a2.z = fmaf(e2, xv.z, a2.z); a2.w = fmaf(e2, xv.w, a2.w);
            a3.x = fmaf(e3, xv.x, a3.x); a3.y = fmaf(e3, xv.y, a3.y);
            a3.z = fmaf(e3, xv.z, a3.z); a3.w = fmaf(e3, xv.w, a3.w);
            dn0 += e0; dn1 += e1; dn2 += e2; dn3 += e3;
        }
        // cross-warp combine in smem: part[warp][head][lane]
        part[w][0][lane] = a0; part[w][1][lane] = a1;
        part[w][2][lane] = a2; part[w][3][lane] = a3;
        if (lane == 0) { pdn[w][0] = dn0; pdn[w][1] = dn1; pdn[w][2] = dn2; pdn[w][3] = dn3; }
        __syncthreads();
        // thread t = (h=w, lane) finalizes head w
        int h = w;
        float4 s0 = part[0][h][lane], s1 = part[1][h][lane];
        float4 s2 = part[2][h][lane], s3 = part[3][h][lane];
        float4 u;
        u.x = s0.x + s1.x + s2.x + s3.x;
        u.y = s0.y + s1.y + s2.y + s3.y;
        u.z = s0.z + s1.z + s2.z + s3.z;
        u.w = s0.w + s1.w + s2.w + s3.w;
        float dn = pdn[0][h] + pdn[1][h] + pdn[2][h] + pdn[3][h];
        float inv = dn > 0.f ? 1.0f / dn : 0.f;
        u.x *= inv; u.y *= inv; u.z *= inv; u.w *= inv;
        ((float4*)d_u)[(size_t)r * 128 + h * 32 + lane] = u;
        if (t == 0) d_flag[r] = (end > start) ? 1.0f : 0.0f;
        __syncthreads();   // part[] safe to reuse; sreg safe to rewrite
    }
    #undef DOT4
}

// ---------------- K3: batched epilogue — each thread applies its weight row to 8 regions ----------------
// Block: 512 threads = 2 groups of 128; group g handles regions [blk*16 + 8g, +8).
// Weight float4 read ONCE serves 8 regions; 8 independent FMA chains hide LDS latency.
// 2000 = 125 blocks * 16 regions exactly -> no bounds checks.
__global__ void __launch_bounds__(512) k_epilogue(
        const float* __restrict__ Wv, const float* __restrict__ bv,
        const float* __restrict__ Wo, const float* __restrict__ bo,
        const float* __restrict__ Wg) {
    extern __shared__ float sm[];
    float* Wv_s = sm;
    float* Wo_s = Wv_s + DIM * WPITCH;
    float* Wg_s = Wo_s + DIM * WPITCH;
    float* O_s  = Wg_s + DIM * WPITCH;   // 16 regions x 128
    float* O2_s = O_s + 16 * DIM;        // 16 regions x 128
    int t = threadIdx.x;
    int sub = t >> 7;      // group id (0..1) -- wait, 512 threads = 4 subs of 128
    int tt = t & 127;      // output element / weight row
    int h = tt >> 5;       // head for stage 1
    // NOTE: 512 threads / 128 = 4 sub-slots, but we use 2 groups of 8 regions:
    // groups are sub>>1; the two half-groups duplicate work split by region parity.
    // Simpler: sub in 0..3 each handles 4 regions? No -- we want G=8.
    // Reorganize: group = t >> 8 (0..1), tt = t & 255 -> 256 threads/group is wrong for 128-row matvec.
    // Correct scheme: 2 groups of 256 threads; within group, thread pair (tt, tt+128) splits
    // the 8 regions 4/4. tt2 = t & 255; row = tt2 & 127; half = tt2 >> 7.
    int grp = t >> 8;          // 0..1
    int tl = t & 255;          // thread in group
    int row = tl & 127;        // weight row / output element
    int half = tl >> 7;        // which 4 of the group's 8 regions
    h = row >> 5;
    for (int idx = t; idx < DIM * DIM / 4; idx += 512) {
        int r4 = idx >> 5, col4 = idx & 31;
        float4 v0 = ((const float4*)Wv)[idx];
        float4 v1 = ((const float4*)Wo)[idx];
        float4 v2 = ((const float4*)Wg)[idx];
        *(float4*)(Wv_s + r4 * WPITCH + col4 * 4) = v0;
        *(float4*)(Wo_s + r4 * WPITCH + col4 * 4) = v1;
        *(float4*)(Wg_s + r4 * WPITCH + col4 * 4) = v2;
    }
    float qv = d_q[row], bvv = bv[row], bov = bo[row];
    int rbase = blockIdx.x * 16 + grp * 8 + half * 4;  // 4 consecutive regions for this thread
    int slot = grp * 8 + half * 4;
    __syncthreads();                             // weights visible to all
    // ---- stage 1: O = q + Wv . u + flag*bv   (4 regions per thread; 8 per weight-row pair) ----
    {
        const float4* wr = (const float4*)(Wv_s + row * WPITCH);
        const float4* u0 = (const float4*)(d_u + (size_t)(rbase + 0) * 512 + h * 128);
        const float4* u1 = (const float4*)(d_u + (size_t)(rbase + 1) * 512 + h * 128);
        const float4* u2 = (const float4*)(d_u + (size_t)(rbase + 2) * 512 + h * 128);
        const float4* u3 = (const float4*)(d_u + (size_t)(rbase + 3) * 512 + h * 128);
        float a0 = 0.f, a1 = 0.f, a2 = 0.f, a3 = 0.f;
        #pragma unroll
        for (int i = 0; i < DIM / 4; i++) {
            float4 w = wr[i];
            float4 v0 = __ldg(&u0[i]);
            float4 v1 = __ldg(&u1[i]);
            float4 v2 = __ldg(&u2[i]);
            float4 v3 = __ldg(&u3[i]);
            a0 = fmaf(w.x, v0.x, a0); a0 = fmaf(w.y, v0.y, a0);
            a0 = fmaf(w.z, v0.z, a0); a0 = fmaf(w.w, v0.w, a0);
            a1 = fmaf(w.x, v1.x, a1); a1 = fmaf(w.y, v1.y, a1);
            a1 = fmaf(w.z, v1.z, a1); a1 = fmaf(w.w, v1.w, a1);
            a2 = fmaf(w.x, v2.x, a2); a2 = fmaf(w.y, v2.y, a2);
            a2 = fmaf(w.z, v2.z, a2); a2 = fmaf(w.w, v2.w, a2);
            a3 = fmaf(w.x, v3.x, a3); a3 = fmaf(w.y, v3.y, a3);
            a3 = fmaf(w.z, v3.z, a3); a3 = fmaf(w.w, v3.w, a3);
        }
        O_s[(slot + 0) * DIM + row] = qv + a0 + d_flag[rbase + 0] * bvv;
        O_s[(slot + 1) * DIM + row] = qv + a1 + d_flag[rbase + 1] * bvv;
        O_s[(slot + 2) * DIM + row] = qv + a2 + d_flag[rbase + 2] * bvv;
        O_s[(slot + 3) * DIM + row] = qv + a3 + d_flag[rbase + 3] * bvv;
    }
    asm volatile("bar.sync %0, %1;" :: "r"(grp + 1), "r"(256) : "memory");
    // ---- stage 2: O2 = O + relu(Wo . O + bo) ----
    {
        const float4* wr = (const float4*)(Wo_s + row * WPITCH);
        const float4* o0 = (const float4*)(O_s + (slot + 0) * DIM);
        const float4* o1 = (const float4*)(O_s + (slot + 1) * DIM);
        const float4* o2 = (const float4*)(O_s + (slot + 2) * DIM);
        const float4* o3 = (const float4*)(O_s + (slot + 3) * DIM);
        float a0 = bov, a1 = bov, a2 = bov, a3 = bov;
        #pragma unroll
        for (int i = 0; i < DIM / 4; i++) {
            float4 w = wr[i];
            float4 v0 = o0[i];
            float4 v1 = o1[i];
            float4 v2 = o2[i];
            float4 v3 = o3[i];
            a0 = fmaf(w.x, v0.x, a0); a0 = fmaf(w.y, v0.y, a0);
            a0 = fmaf(w.z, v0.z, a0); a0 = fmaf(w.w, v0.w, a0);
            a1 = fmaf(w.x, v1.x, a1); a1 = fmaf(w.y, v1.y, a1);
            a1 = fmaf(w.z, v1.z, a1); a1 = fmaf(w.w, v1.w, a1);
            a2 = fmaf(w.x, v2.x, a2); a2 = fmaf(w.y, v2.y, a2);
            a2 = fmaf(w.z, v2.z, a2); a2 = fmaf(w.w, v2.w, a2);
            a3 = fmaf(w.x, v3.x, a3); a3 = fmaf(w.y, v3.y, a3);
            a3 = fmaf(w.z, v3.z, a3); a3 = fmaf(w.w, v3.w, a3);
        }
        O2_s[(slot + 0) * DIM + row] = O_s[(slot + 0) * DIM + row] + fmaxf(a0, 0.f);
        O2_s[(slot + 1) * DIM + row] = O_s[(slot + 1) * DIM + row] + fmaxf(a1, 0.f);
        O2_s[(slot + 2) * DIM + row] = O_s[(slot + 2) * DIM + row] + fmaxf(a2, 0.f);
        O2_s[(slot + 3) * DIM + row] = O_s[(slot + 3) * DIM + row] + fmaxf(a3, 0.f);
    }
    asm volatile("bar.sync %0, %1;" :: "r"(grp + 1), "r"(256) : "memory");
    // ---- stage 3: h = Wg . O2 -> global ----
    {
        const float4* wr = (const float4*)(Wg_s + row * WPITCH);
        const float4* o0 = (const float4*)(O2_s + (slot + 0) * DIM);
        const float4* o1 = (const float4*)(O2_s + (slot + 1) * DIM);
        const float4* o2 = (const float4*)(O2_s + (slot + 2) * DIM);
        const float4* o3 = (const float4*)(O2_s + (slot + 3) * DIM);
        float a0 = 0.f, a1 = 0.f, a2 = 0.f, a3 = 0.f;
        #pragma unroll
        for (int i = 0; i < DIM / 4; i++) {
            float4 w = wr[i];
            float4 v0 = o0[i];
            float4 v1 = o1[i];
            float4 v2 = o2[i];
            float4 v3 = o3[i];
            a0 = fmaf(w.x, v0.x, a0); a0 = fmaf(w.y, v0.y, a0);
            a0 = fmaf(w.z, v0.z, a0); a0 = fmaf(w.w, v0.w, a0);
            a1 = fmaf(w.x, v1.x, a1); a1 = fmaf(w.y, v1.y, a1);
            a1 = fmaf(w.z, v1.z, a1); a1 = fmaf(w.w, v1.w, a1);
            a2 = fmaf(w.x, v2.x, a2); a2 = fmaf(w.y, v2.y, a2);
            a2 = fmaf(w.z, v2.z, a2); a2 = fmaf(w.w, v2.w, a2);
            a3 = fmaf(w.x, v3.x, a3); a3 = fmaf(w.y, v3.y, a3);
            a3 = fmaf(w.z, v3.z, a3); a3 = fmaf(w.w, v3.w, a3);
        }
        d_hbuf[(size_t)(rbase + 0) * DIM + row] = a0;
        d_hbuf[(size_t)(rbase + 1) * DIM + row] = a1;
        d_hbuf[(size_t)(rbase + 2) * DIM + row] = a2;
        d_hbuf[(size_t)(rbase + 3) * DIM + row] = a3;
    }
}

// ---------------- K4: edge scatter out[dst] += norm * h[src] (warp per edge) ----------------
__global__ void k_edge(const int* __restrict__ adj, int E, float* __restrict__ out) {
    int widx = (blockIdx.x * blockDim.x + threadIdx.x) >> 5;
    int lane = threadIdx.x & 31;
    if (widx >= E) return;
    int s = adj[widx], d = adj[E + widx];
    float norm = rsqrtf(fmaxf(d_deg[s], 1e-12f)) * rsqrtf(fmaxf(d_deg[d], 1e-12f));
    const float* hr = d_hbuf + (size_t)s * DIM;
    float* orow = out + (size_t)d * DIM;
    #pragma unroll
    for (int j = lane; j < DIM; j += 32)
        atomicAdd(&orow[j], norm * hr[j]);
}

// ---------------- K5: self loop + PReLU ----------------
__global__ void k_final(const float* __restrict__ prelu, float* __restrict__ out) {
    int idx = blockIdx.x * blockDim.x + threadIdx.x;
    if (idx >= R_REG * DIM) return;
    int r = idx >> 7, j = idx & 127;
    float dis = rsqrtf(fmaxf(d_deg[r], 1e-12f));
    float val = out[idx] + dis * dis * d_hbuf[idx];
    out[idx] = val > 0.f ? val : prelu[j] * val;
}

// ---------------- launch ----------------
extern "C" void kernel_launch(void* const* d_in, const int* in_sizes, int n_in,
                              void* d_out, int out_size) {
    const float* x    = (const float*)d_in[0];
    const int*   zone = (const int*)d_in[1];
    const int*   adj  = (const int*)d_in[2];
    const float* S    = (const float*)d_in[3];
    const float* Wq   = (const float*)d_in[4];
    const float* bq   = (const float*)d_in[5];
    const float* Wk   = (const float*)d_in[6];
    const float* bk   = (const float*)d_in[7];
    const float* Wv   = (const float*)d_in[8];
    const float* bv   = (const float*)d_in[9];
    const float* Wo   = (const float*)d_in[10];
    const float* bo   = (const float*)d_in[11];
    const float* Wg   = (const float*)d_in[12];
    const float* bg   = (const float*)d_in[13];
    const float* prelu = (const float*)d_in[14];
    float* out = (float*)d_out;
    int N = in_sizes[0] / DIM;
    int E = in_sizes[2] / 2;

    // K0: init + histogram + fused scan + setup
    int nbI = (R_REG * DIM + 255) / 256;
    int nbH = (N + HIST_CHUNK - 1) / HIST_CHUNK;
    k_init_setup<<<nbI + nbH + 1, 256>>>(bg, out, S, Wq, bq, Wk, bk, zone, N, nbI, nbH);

    // K1: counting-sort scatter (4 pts/thread) + deg blocks
    int nbS = (N + 1023) / 1024;
    int nbD = (E + 255) / 256;
    k_sort<<<nbS + nbD, 256>>>(zone, adj, N, E, nbS);

    // K2: persistent fused score+accumulate — dynamic region stealing
    k_accum<<<ACC_BLOCKS, 128>>>(x);

    // K3: batched epilogue — 16 regions per 512-thread block, weight reads shared 8x
    int smem_epi = (3 * DIM * WPITCH + 32 * DIM) * (int)sizeof(float);
    cudaFuncSetAttribute(k_epilogue, cudaFuncAttributeMaxDynamicSharedMemorySize, smem_epi);
    k_epilogue<<<R_REG / 16, 512, smem_epi>>>(Wv, bv, Wo, bo, Wg);

    k_edge<<<(E * 32 + 255) / 256, 256>>>(adj, E, out);
    k_final<<<(R_REG * DIM + 255) / 256, 256>>>(prelu, out);
}